// round 12
// baseline (speedup 1.0000x reference)
#include <cuda_runtime.h>
#include <cuda_bf16.h>
#include <cstdint>
#include <cstdio>
#include <math.h>

#define BATCH   8
#define SEQ     2048
#define TOK     (BATCH*SEQ)      // 16384
#define INF_    256
#define EMBED   512
#define HEADS   8
#define HD      64
#define FFN_    2048
#define NW      8
#define CLASSES 1000

// ---------------- scratch (device globals: allocation-free contract) ----------------
__device__ float g_h[TOK*EMBED];              // residual stream (fp32)
__device__ __nv_bfloat16 g_w2b[2*EMBED*FFN_]; // W2 in bf16
__device__ __nv_bfloat16 g_ocb[TOK*64];       // attention out rank-8, bf16
__device__ __nv_bfloat16 g_ub[2*EMBED*64];    // U in bf16
__device__ __nv_bfloat16 g_xcat[TOK*768];     // [xh | xh | xl]
__device__ __nv_bfloat16 g_wcat[EMBED*768];   // [wih | wil | wih]
__device__ float g_weff[2*3*EMBED*NW];
__device__ float g_m[2*HEADS*NW*NW];
__device__ float g_Tp[4][BATCH*512];          // moment partials (4 chunks)
__device__ float g_Gp[4][BATCH*64];
__device__ float g_S0p[4][BATCH*8];
__device__ float g_pool[BATCH*EMBED];
__device__ float g_poolp[BATCH*16*EMBED];
__device__ float g_pe[SEQ*EMBED];

__device__ __forceinline__ unsigned pack_bf2(float lo, float hi) {
    __nv_bfloat162 v = __float22bfloat162_rn(make_float2(lo, hi));
    return *(unsigned*)&v;
}

// ================= fat setup kernel 1: pe | splitx | splitw | w2b | eff ============
#define SB_PE    2048
#define SB_SX    (SB_PE + 16384)
#define SB_SW    (SB_SX + 512)
#define SB_W2    (SB_SW + 8192)
#define SB_EFF   (SB_W2 + 192)
__global__ __launch_bounds__(256) void setup1_kernel(
    const float* __restrict__ x, const float* __restrict__ Wi,
    const float* __restrict__ W2,
    const float* __restrict__ Wq, const float* __restrict__ Wk,
    const float* __restrict__ Wv, const float* __restrict__ Wp)
{
    int blk = blockIdx.x, tid = threadIdx.x;
    if (blk < SB_PE) {
        int s = blk, j = tid;
        double div = exp(-(double)(2*j) * log(10000.0) / (double)EMBED);
        double ang = fmod((double)s * div, 6.283185307179586476925286766559);
        if (ang > 3.14159265358979323846) ang -= 6.283185307179586476925286766559;
        float a = (float)ang;
        g_pe[(size_t)s*EMBED + 2*j]     = __sinf(a);
        g_pe[(size_t)s*EMBED + 2*j + 1] = __cosf(a);
    } else if (blk < SB_SX) {
        int i = (blk - SB_PE)*256 + tid;
        int t = i / INF_, k = i % INF_;
        float v = x[i];
        __nv_bfloat16 h = __float2bfloat16(v);
        __nv_bfloat16 l = __float2bfloat16(v - __bfloat162float(h));
        size_t b = (size_t)t*768 + k;
        g_xcat[b] = h; g_xcat[b+256] = h; g_xcat[b+512] = l;
    } else if (blk < SB_SW) {
        int i = (blk - SB_SX)*256 + tid;
        int n = i / INF_, k = i % INF_;
        float v = Wi[i];
        __nv_bfloat16 h = __float2bfloat16(v);
        __nv_bfloat16 l = __float2bfloat16(v - __bfloat162float(h));
        size_t b = (size_t)n*768 + k;
        g_wcat[b] = h; g_wcat[b+256] = l; g_wcat[b+512] = h;
    } else if (blk < SB_W2) {
        int i = (blk - SB_SW)*256 + tid;
        g_w2b[i] = __float2bfloat16(W2[i]);
    } else {
        int idx = (blk - SB_W2)*256 + tid;
        int l   = idx / (3*EMBED*NW);
        int r   = idx % (3*EMBED*NW);
        int mat = r / (EMBED*NW);
        int r2  = r % (EMBED*NW);
        int f   = r2 / NW;
        int w   = r2 % NW;
        const float* W = (mat==0 ? Wq : (mat==1 ? Wk : Wv)) + (size_t)l*EMBED*EMBED + (size_t)f*EMBED;
        const float* P = Wp + (size_t)l*EMBED*NW + w;
        float s = 0.f;
        for (int e = 0; e < EMBED; e++) s = fmaf(W[e], P[(size_t)e*NW], s);
        g_weff[idx] = s;
    }
}

// ================= fat setup kernel 2: mh | u ======================================
__global__ __launch_bounds__(512) void setup2_kernel(const float* __restrict__ Wo) {
    int blk = blockIdx.x, tid = threadIdx.x;
    if (blk < 2) {
        int l = blk;
        int h = tid >> 6, uv = tid & 63, u = uv >> 3, v = uv & 7;
        const float* Wq = g_weff + ((size_t)(l*3+0)*EMBED + h*HD)*NW;
        const float* Wk = g_weff + ((size_t)(l*3+1)*EMBED + h*HD)*NW;
        float s = 0.f;
        for (int d = 0; d < HD; d++) s = fmaf(Wq[d*NW + u], Wk[d*NW + v], s);
        g_m[((size_t)l*HEADS + h)*64 + u*8 + v] = s;
    } else {
        int idx = (blk - 2)*512 + tid;
        int l = idx / (EMBED*64);
        int f = (idx / 64) % EMBED;
        int e = idx % 64;
        int h = e >> 3, w = e & 7;
        const float* wo = Wo + ((size_t)l*EMBED + f)*EMBED + h*HD;
        const float* wv = g_weff + ((size_t)(l*3+2)*EMBED + h*HD)*NW + w;
        float s = 0.f;
        for (int d = 0; d < HD; d++) s = fmaf(wo[d], wv[(size_t)d*NW], s);
        g_ub[idx] = __float2bfloat16(s);
    }
}

// ================= attention moment statistics (4-way chunked) =====================
__global__ __launch_bounds__(256) void stats_kernel(const float* __restrict__ theta) {
    const int wsel = blockIdx.x;
    const int b = blockIdx.y;
    const int z = blockIdx.z;
    const int tid = threadIdx.x, lane = tid & 31, wp = tid >> 5;
    __shared__ float red[8*65];
    float acc[64];
    #pragma unroll
    for (int i = 0; i < 64; i++) acc[i] = 0.f;
    float s0 = 0.f;
    float th[8];
    #pragma unroll
    for (int u = 0; u < 8; u++) th[u] = theta[u];

    for (int i = 0; i < 2; i++) {
        int k = b*SEQ + z*512 + i*256 + tid;
        float c[8];
        #pragma unroll
        for (int u = 0; u < 8; u++)
            c[u] = cosf(g_h[(size_t)k*EMBED + u] + th[u]);
        float mult = (wsel < 8) ? c[wsel] : 1.f;
        s0 += mult;
        float mc[8];
        #pragma unroll
        for (int u = 0; u < 8; u++) mc[u] = mult*c[u];
        #pragma unroll
        for (int u = 0; u < 8; u++)
            #pragma unroll
            for (int v = 0; v < 8; v++)
                acc[u*8+v] = fmaf(mc[u], c[v], acc[u*8+v]);
    }
    #pragma unroll
    for (int o = 16; o; o >>= 1) {
        #pragma unroll
        for (int i = 0; i < 64; i++) acc[i] += __shfl_xor_sync(0xffffffffu, acc[i], o);
        s0 += __shfl_xor_sync(0xffffffffu, s0, o);
    }
    if (lane == 0) {
        #pragma unroll
        for (int i = 0; i < 64; i++) red[wp*65 + i] = acc[i];
        red[wp*65 + 64] = s0;
    }
    __syncthreads();
    if (tid < 64) {
        float s = 0.f;
        #pragma unroll
        for (int w2 = 0; w2 < 8; w2++) s += red[w2*65 + tid];
        if (wsel < 8) g_Tp[z][b*512 + tid*8 + wsel] = s;
        else          g_Gp[z][b*64 + tid] = s;
    }
    if (tid == 64 && wsel < 8) {
        float s = 0.f;
        #pragma unroll
        for (int w2 = 0; w2 < 8; w2++) s += red[w2*65 + 64];
        g_S0p[z][b*8 + wsel] = s;
    }
}

// ================= attention evaluation (series softmax) ===========================
__global__ __launch_bounds__(256) void eval_kernel(const float* __restrict__ theta,
                                                   const float* __restrict__ M,
                                                   __nv_bfloat16* __restrict__ Oc) {
    __shared__ float Ts[512], Ms[512], Gs[64], S0s[8];
    const int tid = threadIdx.x;
    const int t0 = blockIdx.x*32;
    const int b = t0 >> 11;
    Ts[tid]     = g_Tp[0][b*512+tid]     + g_Tp[1][b*512+tid]
                + g_Tp[2][b*512+tid]     + g_Tp[3][b*512+tid];
    Ts[tid+256] = g_Tp[0][b*512+256+tid] + g_Tp[1][b*512+256+tid]
                + g_Tp[2][b*512+256+tid] + g_Tp[3][b*512+256+tid];
    Ms[tid] = M[tid];           Ms[tid+256] = M[tid+256];
    if (tid < 64) Gs[tid] = g_Gp[0][b*64+tid] + g_Gp[1][b*64+tid]
                          + g_Gp[2][b*64+tid] + g_Gp[3][b*64+tid];
    if (tid < 8)  S0s[tid] = g_S0p[0][b*8+tid] + g_S0p[1][b*8+tid]
                           + g_S0p[2][b*8+tid] + g_S0p[3][b*8+tid];
    __syncthreads();

    const int tok = t0 + (tid >> 3);
    const int h = tid & 7;
    float c[8];
    #pragma unroll
    for (int u = 0; u < 8; u++)
        c[u] = cosf(g_h[(size_t)tok*EMBED + u] + theta[u]);
    float a[8];
    #pragma unroll
    for (int v = 0; v < 8; v++) {
        float s = 0.f;
        #pragma unroll
        for (int u = 0; u < 8; u++) s = fmaf(c[u], Ms[h*64 + u*8 + v], s);
        a[v] = 0.125f*s;
    }
    float num[8];
    float den = (float)SEQ;
    #pragma unroll
    for (int w = 0; w < 8; w++) num[w] = S0s[w];
    #pragma unroll
    for (int u = 0; u < 8; u++) {
        den = fmaf(a[u], S0s[u], den);
        #pragma unroll
        for (int w = 0; w < 8; w++) num[w] = fmaf(a[u], Gs[u*8+w], num[w]);
    }
    #pragma unroll
    for (int u = 0; u < 8; u++)
        #pragma unroll
        for (int v = 0; v < 8; v++) {
            float q = 0.5f*a[u]*a[v];
            den = fmaf(q, Gs[u*8+v], den);
            #pragma unroll
            for (int w = 0; w < 8; w++)
                num[w] = fmaf(q, Ts[(u*8+v)*8 + w], num[w]);
        }
    float inv = 1.f/den;
    uint4 o;
    o.x = pack_bf2(num[0]*inv, num[1]*inv);
    o.y = pack_bf2(num[2]*inv, num[3]*inv);
    o.z = pack_bf2(num[4]*inv, num[5]*inv);
    o.w = pack_bf2(num[6]*inv, num[7]*inv);
    *(uint4*)(Oc + (size_t)tok*64 + h*8) = o;
}

// ---------------- shared mma helpers ------------------------------------------------
__device__ __forceinline__ void ldsm_x4(unsigned& r0, unsigned& r1, unsigned& r2,
                                        unsigned& r3, unsigned addr) {
    asm volatile("ldmatrix.sync.aligned.m8n8.x4.shared.b16 {%0,%1,%2,%3}, [%4];"
                 : "=r"(r0), "=r"(r1), "=r"(r2), "=r"(r3) : "r"(addr));
}
__device__ __forceinline__ void mma16816(float* d, unsigned a0, unsigned a1,
                                         unsigned a2, unsigned a3,
                                         unsigned b0, unsigned b1) {
    asm volatile("mma.sync.aligned.m16n8k16.row.col.f32.bf16.bf16.f32 "
        "{%0,%1,%2,%3}, {%4,%5,%6,%7}, {%8,%9}, {%0,%1,%2,%3};"
        : "+f"(d[0]), "+f"(d[1]), "+f"(d[2]), "+f"(d[3])
        : "r"(a0), "r"(a1), "r"(a2), "r"(a3), "r"(b0), "r"(b1));
}

// ---------------- bf16 mma.sync NT GEMM (input projection only) --------------------
#define SROW 40
#define GSTAGES 3
#define GSMEM (GSTAGES*2*128*SROW*2)
__device__ __forceinline__ void cp_stage(
    const __nv_bfloat16* A, const __nv_bfloat16* B, int K, int m0, int n0,
    int tid, unsigned asb, unsigned bsb, unsigned stageB, int kt, int buf)
{
    #pragma unroll
    for (int half = 0; half < 2; half++) {
        int s = tid + half*256;
        int r = s >> 2, cch = s & 3;
        const __nv_bfloat16* ga = A + (size_t)(m0+r)*K + kt*32 + cch*8;
        unsigned sa = asb + (unsigned)buf*stageB + (unsigned)(r*SROW + cch*8)*2u;
        asm volatile("cp.async.cg.shared.global [%0], [%1], 16;" :: "r"(sa), "l"(ga));
        const __nv_bfloat16* gb = B + (size_t)(n0+r)*K + kt*32 + cch*8;
        unsigned sb = bsb + (unsigned)buf*stageB + (unsigned)(r*SROW + cch*8)*2u;
        asm volatile("cp.async.cg.shared.global [%0], [%1], 16;" :: "r"(sb), "l"(gb));
    }
    asm volatile("cp.async.commit_group;");
}
__global__ __launch_bounds__(256) void gemm_bf16(
    const __nv_bfloat16* __restrict__ A, const __nv_bfloat16* __restrict__ B,
    float* __restrict__ Cf, int K, int N,
    const float* __restrict__ bias, int pe)
{
    extern __shared__ __nv_bfloat16 smem[];
    const int tid  = threadIdx.x;
    const int lane = tid & 31, warp = tid >> 5;
    const int wm = warp & 3, wn = warp >> 2;
    const int m0 = blockIdx.y*128, n0 = blockIdx.x*128;

    const unsigned asb = (unsigned)__cvta_generic_to_shared(smem);
    const unsigned bsb = asb + GSTAGES*128*SROW*2;
    const unsigned stageB = 128*SROW*2;

    float acc[2][8][4];
    #pragma unroll
    for (int i=0;i<2;i++)
        #pragma unroll
        for (int j=0;j<8;j++)
            #pragma unroll
            for (int q=0;q<4;q++) acc[i][j][q]=0.f;

    const int NK = K/32;
    cp_stage(A, B, K, m0, n0, tid, asb, bsb, stageB, 0, 0);
    if (NK > 1) cp_stage(A, B, K, m0, n0, tid, asb, bsb, stageB, 1, 1);

    for (int kt = 0; kt < NK; kt++) {
        const int buf = kt % GSTAGES;
        if (kt + 1 < NK) asm volatile("cp.async.wait_group 1;");
        else             asm volatile("cp.async.wait_group 0;");
        __syncthreads();
        if (kt + 2 < NK)
            cp_stage(A, B, K, m0, n0, tid, asb, bsb, stageB, kt+2, (kt+2)%GSTAGES);

        #pragma unroll
        for (int kk = 0; kk < 2; kk++) {
            unsigned a[2][4];
            #pragma unroll
            for (int mt = 0; mt < 2; mt++) {
                int r = lane & 15, kh = lane >> 4;
                unsigned addr = asb + (unsigned)buf*stageB +
                    (unsigned)((wm*32 + mt*16 + r)*SROW + kk*16 + kh*8)*2u;
                ldsm_x4(a[mt][0], a[mt][1], a[mt][2], a[mt][3], addr);
            }
            unsigned b[8][2];
            #pragma unroll
            for (int p = 0; p < 4; p++) {
                int n  = wn*64 + p*16 + ((lane >> 4) & 1)*8 + (lane & 7);
                int kh = (lane >> 3) & 1;
                unsigned addr = bsb + (unsigned)buf*stageB +
                    (unsigned)(n*SROW + kk*16 + kh*8)*2u;
                ldsm_x4(b[2*p][0], b[2*p][1], b[2*p+1][0], b[2*p+1][1], addr);
            }
            #pragma unroll
            for (int mt = 0; mt < 2; mt++)
                #pragma unroll
                for (int nt = 0; nt < 8; nt++)
                    mma16816(acc[mt][nt], a[mt][0], a[mt][1], a[mt][2], a[mt][3],
                             b[nt][0], b[nt][1]);
        }
        __syncthreads();
    }

    #pragma unroll
    for (int mt = 0; mt < 2; mt++) {
        int row = m0 + wm*32 + mt*16 + (lane >> 2);
        int s = row & (SEQ-1);
        #pragma unroll
        for (int nt = 0; nt < 8; nt++) {
            int col = n0 + wn*64 + nt*8 + (lane & 3)*2;
            float2 v0 = make_float2(acc[mt][nt][0], acc[mt][nt][1]);
            float2 v1 = make_float2(acc[mt][nt][2], acc[mt][nt][3]);
            if (bias) {
                v0.x += bias[col]; v0.y += bias[col+1];
                v1.x += bias[col]; v1.y += bias[col+1];
            }
            if (pe) {
                v0.x += g_pe[(size_t)s*EMBED + col];
                v0.y += g_pe[(size_t)s*EMBED + col + 1];
                v1.x += g_pe[(size_t)(s+8)*EMBED + col];
                v1.y += g_pe[(size_t)(s+8)*EMBED + col + 1];
            }
            *(float2*)(Cf + (size_t)row*N + col)     = v0;
            *(float2*)(Cf + (size_t)(row+8)*N + col) = v1;
        }
    }
}

// ============ fused Wo-GEMM + residual + LayerNorm (32 tok x 512) ==================
#define WROW 72
#define WO_SMEM (512*WROW*2 + 32*WROW*2 + 2048 + 256)
__global__ __launch_bounds__(256) void gemm_wo_ln(
    const __nv_bfloat16* __restrict__ Oc, const __nv_bfloat16* __restrict__ U,
    const float* __restrict__ gg, const float* __restrict__ bb)
{
    extern __shared__ char ds[];
    const unsigned bsb = (unsigned)__cvta_generic_to_shared(ds);
    const unsigned asb = bsb + 512*WROW*2;
    float* part_s = (float*)(ds + 512*WROW*2 + 32*WROW*2);
    float* part_q = part_s + 256;
    float2* stats = (float2*)(part_q + 256);

    const int tid = threadIdx.x, lane = tid & 31, w = tid >> 5;
    const int t0 = blockIdx.x*32;

    #pragma unroll
    for (int i = 0; i < 16; i++) {
        int s = tid + i*256;
        int r = s >> 3, ch = s & 7;
        unsigned sa = bsb + (unsigned)(r*WROW + ch*8)*2u;
        asm volatile("cp.async.cg.shared.global [%0], [%1], 16;"
                     :: "r"(sa), "l"(U + (size_t)r*64 + ch*8));
    }
    {
        int r = tid >> 3, ch = tid & 7;
        unsigned sa = asb + (unsigned)(r*WROW + ch*8)*2u;
        asm volatile("cp.async.cg.shared.global [%0], [%1], 16;"
                     :: "r"(sa), "l"(Oc + (size_t)(t0+r)*64 + ch*8));
    }
    asm volatile("cp.async.commit_group;");
    asm volatile("cp.async.wait_group 0;");
    __syncthreads();

    float acc[2][8][4];
    #pragma unroll
    for (int i=0;i<2;i++)
        #pragma unroll
        for (int j=0;j<8;j++)
            #pragma unroll
            for (int q=0;q<4;q++) acc[i][j][q]=0.f;

    #pragma unroll
    for (int kk = 0; kk < 4; kk++) {
        unsigned a[2][4];
        #pragma unroll
        for (int mt = 0; mt < 2; mt++) {
            int r = lane & 15, kh = lane >> 4;
            unsigned addr = asb + (unsigned)((mt*16 + r)*WROW + kk*16 + kh*8)*2u;
            ldsm_x4(a[mt][0], a[mt][1], a[mt][2], a[mt][3], addr);
        }
        unsigned b[8][2];
        #pragma unroll
        for (int p = 0; p < 4; p++) {
            int n  = w*64 + p*16 + ((lane >> 4) & 1)*8 + (lane & 7);
            int kh = (lane >> 3) & 1;
            unsigned addr = bsb + (unsigned)(n*WROW + kk*16 + kh*8)*2u;
            ldsm_x4(b[2*p][0], b[2*p][1], b[2*p+1][0], b[2*p+1][1], addr);
        }
        #pragma unroll
        for (int mt = 0; mt < 2; mt++)
            #pragma unroll
            for (int nt = 0; nt < 8; nt++)
                mma16816(acc[mt][nt], a[mt][0], a[mt][1], a[mt][2], a[mt][3],
                         b[nt][0], b[nt][1]);
    }

    float sum[2][2] = {{0.f,0.f},{0.f,0.f}};
    float sq [2][2] = {{0.f,0.f},{0.f,0.f}};
    #pragma unroll
    for (int mt = 0; mt < 2; mt++) {
        int row = mt*16 + (lane >> 2);
        #pragma unroll
        for (int nt = 0; nt < 8; nt++) {
            int col = w*64 + nt*8 + (lane & 3)*2;
            float2 h0 = *(const float2*)(g_h + (size_t)(t0+row)*EMBED + col);
            float2 h1 = *(const float2*)(g_h + (size_t)(t0+row+8)*EMBED + col);
            acc[mt][nt][0] += h0.x; acc[mt][nt][1] += h0.y;
            acc[mt][nt][2] += h1.x; acc[mt][nt][3] += h1.y;
            sum[mt][0] += acc[mt][nt][0] + acc[mt][nt][1];
            sum[mt][1] += acc[mt][nt][2] + acc[mt][nt][3];
            sq[mt][0]  += acc[mt][nt][0]*acc[mt][nt][0] + acc[mt][nt][1]*acc[mt][nt][1];
            sq[mt][1]  += acc[mt][nt][2]*acc[mt][nt][2] + acc[mt][nt][3]*acc[mt][nt][3];
        }
    }
    #pragma unroll
    for (int o = 1; o < 4; o <<= 1) {
        #pragma unroll
        for (int mt = 0; mt < 2; mt++)
            #pragma unroll
            for (int hf = 0; hf < 2; hf++) {
                sum[mt][hf] += __shfl_xor_sync(0xffffffffu, sum[mt][hf], o);
                sq[mt][hf]  += __shfl_xor_sync(0xffffffffu, sq[mt][hf], o);
            }
    }
    if ((lane & 3) == 0) {
        int r0 = lane >> 2;
        #pragma unroll
        for (int mt = 0; mt < 2; mt++)
            #pragma unroll
            for (int hf = 0; hf < 2; hf++) {
                int row = mt*16 + hf*8 + r0;
                part_s[row*8 + w] = sum[mt][hf];
                part_q[row*8 + w] = sq[mt][hf];
            }
    }
    __syncthreads();
    {
        int row = tid >> 3;
        float s1 = part_s[tid], s2 = part_q[tid];
        #pragma unroll
        for (int o = 1; o < 8; o <<= 1) {
            s1 += __shfl_xor_sync(0xffffffffu, s1, o);
            s2 += __shfl_xor_sync(0xffffffffu, s2, o);
        }
        if ((tid & 7) == 0) {
            float mu  = s1 * (1.f/EMBED);
            float var = s2 * (1.f/EMBED) - mu*mu;
            stats[row] = make_float2(mu, rsqrtf(var + 1e-5f));
        }
    }
    __syncthreads();
    #pragma unroll
    for (int mt = 0; mt < 2; mt++) {
        int row = mt*16 + (lane >> 2);
        float2 s0 = stats[row], s1 = stats[row+8];
        #pragma unroll
        for (int nt = 0; nt < 8; nt++) {
            int col = w*64 + nt*8 + (lane & 3)*2;
            float2 gv = *(const float2*)(gg + col);
            float2 bv = *(const float2*)(bb + col);
            float2 o0, o1;
            o0.x = (acc[mt][nt][0] - s0.x)*s0.y*gv.x + bv.x;
            o0.y = (acc[mt][nt][1] - s0.x)*s0.y*gv.y + bv.y;
            o1.x = (acc[mt][nt][2] - s1.x)*s1.y*gv.x + bv.x;
            o1.y = (acc[mt][nt][3] - s1.x)*s1.y*gv.y + bv.y;
            *(float2*)(g_h + (size_t)(t0+row)*EMBED + col)   = o0;
            *(float2*)(g_h + (size_t)(t0+row+8)*EMBED + col) = o1;
        }
    }
}

// ============ fully fused FFN: h = LN(h + relu(cos(h8+phi)·W1^T)·W2^T)·g + b =======
// 64 tokens x full 512 cols x K=2048 per CTA, 512 threads (2x8 warps).
// A (relu hidden) generated in-kernel from rank-8 form; W2 2-stage cp.async.
#define FROW 40
#define FB_STAGE (512*FROW*2)                 // 40960
#define FA_STAGE (64*FROW*2)                  // 5120
#define FF_OFF_A   (2*FB_STAGE)               // 81920
#define FF_OFF_W1  (FF_OFF_A + 2*FA_STAGE)    // 92160
#define FF_OFF_C   (FF_OFF_W1 + 65536)        // 157696
#define FF_OFF_PS  (FF_OFF_C + 2048)          // 159744
#define FF_OFF_PQ  (FF_OFF_PS + 2048)         // 161792
#define FF_OFF_ST  (FF_OFF_PQ + 2048)         // 163840
#define FF_SMEM    (FF_OFF_ST + 512)          // 164352
__global__ __launch_bounds__(512) void ffn_fused(
    const float* __restrict__ phi, const float* __restrict__ W1,
    const __nv_bfloat16* __restrict__ W2, const float* __restrict__ gg,
    const float* __restrict__ bb)
{
    extern __shared__ char ds[];
    const unsigned bsb = (unsigned)__cvta_generic_to_shared(ds);
    const unsigned asb = bsb + FF_OFF_A;
    float* W1s    = (float*)(ds + FF_OFF_W1);
    float* cs     = (float*)(ds + FF_OFF_C);
    float* part_s = (float*)(ds + FF_OFF_PS);
    float* part_q = (float*)(ds + FF_OFF_PQ);
    float2* stats = (float2*)(ds + FF_OFF_ST);

    const int tid = threadIdx.x, lane = tid & 31, warp = tid >> 5;
    const int wm = warp >> 3, wn = warp & 7;     // 2 x 8 warp grid
    const int t0 = blockIdx.x*64;

    // stage W1 (2048x8 fp32 = 64KB) and c (64x8)
    #pragma unroll
    for (int i = 0; i < 8; i++)
        ((float4*)W1s)[tid + i*512] = ((const float4*)W1)[tid + i*512];
    {
        int tok = tid >> 3, w = tid & 7;
        cs[tid] = cosf(g_h[(size_t)(t0+tok)*EMBED + w] + phi[w]);
    }
    __syncthreads();

    // per-thread fixed tokens for A generation
    const int tokA = tid >> 4;           // 0..31
    const int tokB = tokA + 32;
    const int jp   = tid & 15;           // j pair within 32-col tile
    float cA[8], cB[8];
    #pragma unroll
    for (int u = 0; u < 8; u++) { cA[u] = cs[tokA*8+u]; cB[u] = cs[tokB*8+u]; }

    // B(W2) stage loader: 512 rows x 32 cols, 4 chunks of 16B per thread
    auto noop = 0; (void)noop;

    float acc[2][8][4];
    #pragma unroll
    for (int i=0;i<2;i++)
        #pragma unroll
        for (int j=0;j<8;j++)
            #pragma unroll
            for (int q=0;q<4;q++) acc[i][j][q]=0.f;

    // issue B stage kt into buffer buf
    #define FF_ISSUE_B(kt, buf) do {                                             \
        _Pragma("unroll")                                                         \
        for (int cc = 0; cc < 4; cc++) {                                          \
            int s_ = tid + cc*512;                                                \
            int r_ = s_ >> 2, ch_ = s_ & 3;                                       \
            const __nv_bfloat16* gb_ = W2 + (size_t)r_*FFN_ + (kt)*32 + ch_*8;    \
            unsigned sb_ = bsb + (unsigned)(buf)*FB_STAGE +                       \
                           (unsigned)(r_*FROW + ch_*8)*2u;                        \
            asm volatile("cp.async.cg.shared.global [%0], [%1], 16;"              \
                         :: "r"(sb_), "l"(gb_));                                  \
        }                                                                         \
        asm volatile("cp.async.commit_group;");                                   \
    } while (0)

    FF_ISSUE_B(0, 0);

    for (int kt = 0; kt < FFN_/32; kt++) {
        const int buf = kt & 1;
        // generate A(kt): 64 tokens x 32 j; thread does (tokA,jp*2..+1) & (tokB,..)
        {
            int j0 = kt*32 + jp*2;
            const float* w0 = W1s + j0*8;
            const float* w1 = w0 + 8;
            float a0 = cA[0]*w0[0], a1 = cA[0]*w1[0];
            float b0 = cB[0]*w0[0], b1 = cB[0]*w1[0];
            #pragma unroll
            for (int u = 1; u < 8; u++) {
                a0 = fmaf(cA[u], w0[u], a0); a1 = fmaf(cA[u], w1[u], a1);
                b0 = fmaf(cB[u], w0[u], b0); b1 = fmaf(cB[u], w1[u], b1);
            }
            unsigned pa = pack_bf2(fmaxf(a0,0.f), fmaxf(a1,0.f));
            unsigned pb = pack_bf2(fmaxf(b0,0.f), fmaxf(b1,0.f));
            unsigned* Ap = (unsigned*)(ds + FF_OFF_A + buf*FA_STAGE);
            Ap[(tokA*FROW + jp*2) >> 1] = pa;
            Ap[(tokB*FROW + jp*2) >> 1] = pb;
        }
        asm volatile("cp.async.wait_group 0;");
        __syncthreads();
        if (kt + 1 < FFN_/32) FF_ISSUE_B(kt+1, buf^1);

        #pragma unroll
        for (int kk = 0; kk < 2; kk++) {
            unsigned a[2][4];
            #pragma unroll
            for (int mt = 0; mt < 2; mt++) {
                int r = lane & 15, kh = lane >> 4;
                unsigned addr = asb + (unsigned)buf*FA_STAGE +
                    (unsigned)((wm*32 + mt*16 + r)*FROW + kk*16 + kh*8)*2u;
                ldsm_x4(a[mt][0], a[mt][1], a[mt][2], a[mt][3], addr);
            }
            unsigned b[8][2];
            #pragma unroll
            for (int p = 0; p < 4; p++) {
                int n  = wn*64 + p*16 + ((lane >> 4) & 1)*8 + (lane & 7);
                int kh = (lane >> 3) & 1;
                unsigned addr = bsb + (unsigned)buf*FB_STAGE +
                    (unsigned)(n*FROW + kk*16 + kh*8)*2u;
                ldsm_x4(b[2*p][0], b[2*p][1], b[2*p+1][0], b[2*p+1][1], addr);
            }
            #pragma unroll
            for (int mt = 0; mt < 2; mt++)
                #pragma unroll
                for (int nt = 0; nt < 8; nt++)
                    mma16816(acc[mt][nt], a[mt][0], a[mt][1], a[mt][2], a[mt][3],
                             b[nt][0], b[nt][1]);
        }
        __syncthreads();
    }

    // residual + LN epilogue over 64 rows
    float sum[2][2] = {{0.f,0.f},{0.f,0.f}};
    float sq [2][2] = {{0.f,0.f},{0.f,0.f}};
    #pragma unroll
    for (int mt = 0; mt < 2; mt++) {
        int row = wm*32 + mt*16 + (lane >> 2);
        #pragma unroll
        for (int nt = 0; nt < 8; nt++) {
            int col = wn*64 + nt*8 + (lane & 3)*2;
            float2 h0 = *(const float2*)(g_h + (size_t)(t0+row)*EMBED + col);
            float2 h1 = *(const float2*)(g_h + (size_t)(t0+row+8)*EMBED + col);
            acc[mt][nt][0] += h0.x; acc[mt][nt][1] += h0.y;
            acc[mt][nt][2] += h1.x; acc[mt][nt][3] += h1.y;
            sum[mt][0] += acc[mt][nt][0] + acc[mt][nt][1];
            sum[mt][1] += acc[mt][nt][2] + acc[mt][nt][3];
            sq[mt][0]  += acc[mt][nt][0]*acc[mt][nt][0] + acc[mt][nt][1]*acc[mt][nt][1];
            sq[mt][1]  += acc[mt][nt][2]*acc[mt][nt][2] + acc[mt][nt][3]*acc[mt][nt][3];
        }
    }
    #pragma unroll
    for (int o = 1; o < 4; o <<= 1) {
        #pragma unroll
        for (int mt = 0; mt < 2; mt++)
            #pragma unroll
            for (int hf = 0; hf < 2; hf++) {
                sum[mt][hf] += __shfl_xor_sync(0xffffffffu, sum[mt][hf], o);
                sq[mt][hf]  += __shfl_xor_sync(0xffffffffu, sq[mt][hf], o);
            }
    }
    if ((lane & 3) == 0) {
        int r0 = lane >> 2;
        #pragma unroll
        for (int mt = 0; mt < 2; mt++)
            #pragma unroll
            for (int hf = 0; hf < 2; hf++) {
                int row = wm*32 + mt*16 + hf*8 + r0;
                part_s[row*8 + wn] = sum[mt][hf];
                part_q[row*8 + wn] = sq[mt][hf];
            }
    }
    __syncthreads();
    {
        int row = tid >> 3;
        float s1 = part_s[tid], s2 = part_q[tid];
        #pragma unroll
        for (int o = 1; o < 8; o <<= 1) {
            s1 += __shfl_xor_sync(0xffffffffu, s1, o);
            s2 += __shfl_xor_sync(0xffffffffu, s2, o);
        }
        if ((tid & 7) == 0) {
            float mu  = s1 * (1.f/EMBED);
            float var = s2 * (1.f/EMBED) - mu*mu;
            stats[row] = make_float2(mu, rsqrtf(var + 1e-5f));
        }
    }
    __syncthreads();
    #pragma unroll
    for (int mt = 0; mt < 2; mt++) {
        int row = wm*32 + mt*16 + (lane >> 2);
        float2 s0 = stats[row], s1 = stats[row+8];
        #pragma unroll
        for (int nt = 0; nt < 8; nt++) {
            int col = wn*64 + nt*8 + (lane & 3)*2;
            float2 gv = *(const float2*)(gg + col);
            float2 bv = *(const float2*)(bb + col);
            float2 o0, o1;
            o0.x = (acc[mt][nt][0] - s0.x)*s0.y*gv.x + bv.x;
            o0.y = (acc[mt][nt][1] - s0.x)*s0.y*gv.y + bv.y;
            o1.x = (acc[mt][nt][2] - s1.x)*s1.y*gv.x + bv.x;
            o1.y = (acc[mt][nt][3] - s1.x)*s1.y*gv.y + bv.y;
            *(float2*)(g_h + (size_t)(t0+row)*EMBED + col)   = o0;
            *(float2*)(g_h + (size_t)(t0+row+8)*EMBED + col) = o1;
        }
    }
}

// ---------------- mean pool, 2-phase -----------------------------------------------
__global__ void pool1_kernel() {
    int ch = blockIdx.x, b = blockIdx.y, e = threadIdx.x;
    float s = 0.f;
    #pragma unroll 4
    for (int i = 0; i < 128; i++)
        s += g_h[((size_t)b*SEQ + ch*128 + i)*EMBED + e];
    g_poolp[((size_t)b*16 + ch)*EMBED + e] = s;
}
__global__ void pool2_kernel() {
    int b = blockIdx.x, e = threadIdx.x;
    float s = 0.f;
    #pragma unroll
    for (int ch = 0; ch < 16; ch++)
        s += g_poolp[((size_t)b*16 + ch)*EMBED + e];
    g_pool[b*EMBED + e] = s * (1.f/SEQ);
}

// ---------------- classifier -------------------------------------------------------
__global__ void cls_kernel(const float* __restrict__ Wc, const float* __restrict__ bc,
                           float* __restrict__ out) {
    int idx = blockIdx.x*blockDim.x + threadIdx.x;
    if (idx >= BATCH*CLASSES) return;
    int b = idx / CLASSES, c = idx % CLASSES;
    const float* p = g_pool + b*EMBED;
    const float* w = Wc + (size_t)c*EMBED;
    float s = bc[c];
    for (int e=0;e<EMBED;e++) s = fmaf(p[e], w[e], s);
    out[idx] = s;
}

// ---------------- launch -----------------------------------------------------------
extern "C" void kernel_launch(void* const* d_in, const int* in_sizes, int n_in,
                              void* d_out, int out_size) {
    const float* x     = (const float*)d_in[0];
    const float* Wi    = (const float*)d_in[1];
    const float* bi    = (const float*)d_in[2];
    const float* theta = (const float*)d_in[3];
    const float* Wproj = (const float*)d_in[4];
    const float* Wq    = (const float*)d_in[5];
    const float* Wk    = (const float*)d_in[6];
    const float* Wv    = (const float*)d_in[7];
    const float* Wo    = (const float*)d_in[8];
    const float* g1    = (const float*)d_in[9];
    const float* b1    = (const float*)d_in[10];
    const float* phi   = (const float*)d_in[11];
    const float* W1    = (const float*)d_in[12];
    const float* W2    = (const float*)d_in[13];
    const float* g2    = (const float*)d_in[14];
    const float* b2    = (const float*)d_in[15];
    const float* Wc    = (const float*)d_in[16];
    const float* bc    = (const float*)d_in[17];
    float* out = (float*)d_out;

    float *p_h, *p_m;
    __nv_bfloat16 *p_w2b, *p_ocb, *p_ub, *p_xcat, *p_wcat;
    cudaGetSymbolAddress((void**)&p_h,    g_h);
    cudaGetSymbolAddress((void**)&p_w2b,  g_w2b);
    cudaGetSymbolAddress((void**)&p_ocb,  g_ocb);
    cudaGetSymbolAddress((void**)&p_ub,   g_ub);
    cudaGetSymbolAddress((void**)&p_m,    g_m);
    cudaGetSymbolAddress((void**)&p_xcat, g_xcat);
    cudaGetSymbolAddress((void**)&p_wcat, g_wcat);

    cudaFuncSetAttribute(gemm_bf16, cudaFuncAttributeMaxDynamicSharedMemorySize, GSMEM);
    cudaFuncSetAttribute(gemm_wo_ln, cudaFuncAttributeMaxDynamicSharedMemorySize, WO_SMEM);
    cudaFuncSetAttribute(ffn_fused, cudaFuncAttributeMaxDynamicSharedMemorySize, FF_SMEM);

    setup1_kernel<<<SB_EFF, 256>>>(x, Wi, W2, Wq, Wk, Wv, Wproj);
    setup2_kernel<<<130, 512>>>(Wo);

    dim3 gg(EMBED/128, TOK/128);
    gemm_bf16<<<gg, 256, GSMEM>>>(p_xcat, p_wcat, p_h, 768, EMBED, bi, 1);

    for (int l = 0; l < 2; l++) {
        stats_kernel<<<dim3(9, BATCH, 4), 256>>>(theta + l*NW);
        eval_kernel<<<TOK/32, 256>>>(theta + l*NW, p_m + (size_t)l*HEADS*64, p_ocb);
        gemm_wo_ln<<<TOK/32, 256, WO_SMEM>>>(p_ocb, p_ub + (size_t)l*EMBED*64,
                                             g1 + l*EMBED, b1 + l*EMBED);
        ffn_fused<<<TOK/64, 512, FF_SMEM>>>(phi + l*NW, W1 + (size_t)l*FFN_*NW,
                                            p_w2b + (size_t)l*EMBED*FFN_,
                                            g2 + l*EMBED, b2 + l*EMBED);
    }

    pool1_kernel<<<dim3(16, BATCH), EMBED>>>();
    pool2_kernel<<<BATCH, EMBED>>>();
    cls_kernel<<<(BATCH*CLASSES + 255)/256, 256>>>(Wc, bc, out);
}

// round 13
// speedup vs baseline: 1.1899x; 1.1899x over previous
#include <cuda_runtime.h>
#include <cuda_bf16.h>
#include <cstdint>
#include <cstdio>
#include <math.h>

#define BATCH   8
#define SEQ     2048
#define TOK     (BATCH*SEQ)      // 16384
#define INF_    256
#define EMBED   512
#define HEADS   8
#define HD      64
#define FFN_    2048
#define NW      8
#define CLASSES 1000

// ---------------- scratch (device globals: allocation-free contract) ----------------
__device__ float g_h[TOK*EMBED];              // residual stream (fp32)
__device__ __nv_bfloat16 g_tmpb[TOK*EMBED];   // ffn_out (bf16)
__device__ __nv_bfloat16 g_fb[TOK*FFN_];      // FFN hidden (relu'd, bf16)
__device__ __nv_bfloat16 g_w2b[2*EMBED*FFN_]; // W2 in bf16
__device__ __nv_bfloat16 g_ocb[TOK*64];       // attention out rank-8, bf16
__device__ __nv_bfloat16 g_ub[2*EMBED*64];    // U in bf16
__device__ __nv_bfloat16 g_xcat[TOK*768];     // [xh | xh | xl]
__device__ __nv_bfloat16 g_wcat[EMBED*768];   // [wih | wil | wih]
__device__ float g_weff[2*3*EMBED*NW];
__device__ float g_m[2*HEADS*NW*NW];
__device__ float g_Tp[4][BATCH*512];          // moment partials (4 chunks)
__device__ float g_Gp[4][BATCH*64];
__device__ float g_S0p[4][BATCH*8];
__device__ float g_pool[BATCH*EMBED];
__device__ float g_poolp[BATCH*16*EMBED];
__device__ float g_pe[SEQ*EMBED];

__device__ __forceinline__ unsigned pack_bf2(float lo, float hi) {
    __nv_bfloat162 v = __float22bfloat162_rn(make_float2(lo, hi));
    return *(unsigned*)&v;
}

// ================= fat setup kernel 1: pe | splitx | splitw | w2b | eff ============
#define SB_PE    2048
#define SB_SX    (SB_PE + 16384)
#define SB_SW    (SB_SX + 512)
#define SB_W2    (SB_SW + 8192)
#define SB_EFF   (SB_W2 + 192)
__global__ __launch_bounds__(256) void setup1_kernel(
    const float* __restrict__ x, const float* __restrict__ Wi,
    const float* __restrict__ W2,
    const float* __restrict__ Wq, const float* __restrict__ Wk,
    const float* __restrict__ Wv, const float* __restrict__ Wp)
{
    int blk = blockIdx.x, tid = threadIdx.x;
    if (blk < SB_PE) {
        int s = blk, j = tid;
        double div = exp(-(double)(2*j) * log(10000.0) / (double)EMBED);
        double ang = fmod((double)s * div, 6.283185307179586476925286766559);
        if (ang > 3.14159265358979323846) ang -= 6.283185307179586476925286766559;
        float a = (float)ang;
        g_pe[(size_t)s*EMBED + 2*j]     = __sinf(a);
        g_pe[(size_t)s*EMBED + 2*j + 1] = __cosf(a);
    } else if (blk < SB_SX) {
        int i = (blk - SB_PE)*256 + tid;
        int t = i / INF_, k = i % INF_;
        float v = x[i];
        __nv_bfloat16 h = __float2bfloat16(v);
        __nv_bfloat16 l = __float2bfloat16(v - __bfloat162float(h));
        size_t b = (size_t)t*768 + k;
        g_xcat[b] = h; g_xcat[b+256] = h; g_xcat[b+512] = l;
    } else if (blk < SB_SW) {
        int i = (blk - SB_SX)*256 + tid;
        int n = i / INF_, k = i % INF_;
        float v = Wi[i];
        __nv_bfloat16 h = __float2bfloat16(v);
        __nv_bfloat16 l = __float2bfloat16(v - __bfloat162float(h));
        size_t b = (size_t)n*768 + k;
        g_wcat[b] = h; g_wcat[b+256] = l; g_wcat[b+512] = h;
    } else if (blk < SB_W2) {
        int i = (blk - SB_SW)*256 + tid;
        g_w2b[i] = __float2bfloat16(W2[i]);
    } else {
        int idx = (blk - SB_W2)*256 + tid;
        int l   = idx / (3*EMBED*NW);
        int r   = idx % (3*EMBED*NW);
        int mat = r / (EMBED*NW);
        int r2  = r % (EMBED*NW);
        int f   = r2 / NW;
        int w   = r2 % NW;
        const float* W = (mat==0 ? Wq : (mat==1 ? Wk : Wv)) + (size_t)l*EMBED*EMBED + (size_t)f*EMBED;
        const float* P = Wp + (size_t)l*EMBED*NW + w;
        float s = 0.f;
        for (int e = 0; e < EMBED; e++) s = fmaf(W[e], P[(size_t)e*NW], s);
        g_weff[idx] = s;
    }
}

// ================= fat setup kernel 2: mh | u ======================================
__global__ __launch_bounds__(512) void setup2_kernel(const float* __restrict__ Wo) {
    int blk = blockIdx.x, tid = threadIdx.x;
    if (blk < 2) {
        int l = blk;
        int h = tid >> 6, uv = tid & 63, u = uv >> 3, v = uv & 7;
        const float* Wq = g_weff + ((size_t)(l*3+0)*EMBED + h*HD)*NW;
        const float* Wk = g_weff + ((size_t)(l*3+1)*EMBED + h*HD)*NW;
        float s = 0.f;
        for (int d = 0; d < HD; d++) s = fmaf(Wq[d*NW + u], Wk[d*NW + v], s);
        g_m[((size_t)l*HEADS + h)*64 + u*8 + v] = s;
    } else {
        int idx = (blk - 2)*512 + tid;
        int l = idx / (EMBED*64);
        int f = (idx / 64) % EMBED;
        int e = idx % 64;
        int h = e >> 3, w = e & 7;
        const float* wo = Wo + ((size_t)l*EMBED + f)*EMBED + h*HD;
        const float* wv = g_weff + ((size_t)(l*3+2)*EMBED + h*HD)*NW + w;
        float s = 0.f;
        for (int d = 0; d < HD; d++) s = fmaf(wo[d], wv[(size_t)d*NW], s);
        g_ub[idx] = __float2bfloat16(s);
    }
}

// ================= attention moment statistics (4-way chunked) =====================
__global__ __launch_bounds__(256) void stats_kernel(const float* __restrict__ theta) {
    const int wsel = blockIdx.x;
    const int b = blockIdx.y;
    const int z = blockIdx.z;
    const int tid = threadIdx.x, lane = tid & 31, wp = tid >> 5;
    __shared__ float red[8*65];
    float acc[64];
    #pragma unroll
    for (int i = 0; i < 64; i++) acc[i] = 0.f;
    float s0 = 0.f;
    float th[8];
    #pragma unroll
    for (int u = 0; u < 8; u++) th[u] = theta[u];

    for (int i = 0; i < 2; i++) {
        int k = b*SEQ + z*512 + i*256 + tid;
        float c[8];
        #pragma unroll
        for (int u = 0; u < 8; u++)
            c[u] = cosf(g_h[(size_t)k*EMBED + u] + th[u]);
        float mult = (wsel < 8) ? c[wsel] : 1.f;
        s0 += mult;
        float mc[8];
        #pragma unroll
        for (int u = 0; u < 8; u++) mc[u] = mult*c[u];
        #pragma unroll
        for (int u = 0; u < 8; u++)
            #pragma unroll
            for (int v = 0; v < 8; v++)
                acc[u*8+v] = fmaf(mc[u], c[v], acc[u*8+v]);
    }
    #pragma unroll
    for (int o = 16; o; o >>= 1) {
        #pragma unroll
        for (int i = 0; i < 64; i++) acc[i] += __shfl_xor_sync(0xffffffffu, acc[i], o);
        s0 += __shfl_xor_sync(0xffffffffu, s0, o);
    }
    if (lane == 0) {
        #pragma unroll
        for (int i = 0; i < 64; i++) red[wp*65 + i] = acc[i];
        red[wp*65 + 64] = s0;
    }
    __syncthreads();
    if (tid < 64) {
        float s = 0.f;
        #pragma unroll
        for (int w2 = 0; w2 < 8; w2++) s += red[w2*65 + tid];
        if (wsel < 8) g_Tp[z][b*512 + tid*8 + wsel] = s;
        else          g_Gp[z][b*64 + tid] = s;
    }
    if (tid == 64 && wsel < 8) {
        float s = 0.f;
        #pragma unroll
        for (int w2 = 0; w2 < 8; w2++) s += red[w2*65 + 64];
        g_S0p[z][b*8 + wsel] = s;
    }
}

// ================= attention evaluation (series softmax) ===========================
__global__ __launch_bounds__(256) void eval_kernel(const float* __restrict__ theta,
                                                   const float* __restrict__ M,
                                                   __nv_bfloat16* __restrict__ Oc) {
    __shared__ float Ts[512], Ms[512], Gs[64], S0s[8];
    const int tid = threadIdx.x;
    const int t0 = blockIdx.x*32;
    const int b = t0 >> 11;
    Ts[tid]     = g_Tp[0][b*512+tid]     + g_Tp[1][b*512+tid]
                + g_Tp[2][b*512+tid]     + g_Tp[3][b*512+tid];
    Ts[tid+256] = g_Tp[0][b*512+256+tid] + g_Tp[1][b*512+256+tid]
                + g_Tp[2][b*512+256+tid] + g_Tp[3][b*512+256+tid];
    Ms[tid] = M[tid];           Ms[tid+256] = M[tid+256];
    if (tid < 64) Gs[tid] = g_Gp[0][b*64+tid] + g_Gp[1][b*64+tid]
                          + g_Gp[2][b*64+tid] + g_Gp[3][b*64+tid];
    if (tid < 8)  S0s[tid] = g_S0p[0][b*8+tid] + g_S0p[1][b*8+tid]
                           + g_S0p[2][b*8+tid] + g_S0p[3][b*8+tid];
    __syncthreads();

    const int tok = t0 + (tid >> 3);
    const int h = tid & 7;
    float c[8];
    #pragma unroll
    for (int u = 0; u < 8; u++)
        c[u] = cosf(g_h[(size_t)tok*EMBED + u] + theta[u]);
    float a[8];
    #pragma unroll
    for (int v = 0; v < 8; v++) {
        float s = 0.f;
        #pragma unroll
        for (int u = 0; u < 8; u++) s = fmaf(c[u], Ms[h*64 + u*8 + v], s);
        a[v] = 0.125f*s;
    }
    float num[8];
    float den = (float)SEQ;
    #pragma unroll
    for (int w = 0; w < 8; w++) num[w] = S0s[w];
    #pragma unroll
    for (int u = 0; u < 8; u++) {
        den = fmaf(a[u], S0s[u], den);
        #pragma unroll
        for (int w = 0; w < 8; w++) num[w] = fmaf(a[u], Gs[u*8+w], num[w]);
    }
    #pragma unroll
    for (int u = 0; u < 8; u++)
        #pragma unroll
        for (int v = 0; v < 8; v++) {
            float q = 0.5f*a[u]*a[v];
            den = fmaf(q, Gs[u*8+v], den);
            #pragma unroll
            for (int w = 0; w < 8; w++)
                num[w] = fmaf(q, Ts[(u*8+v)*8 + w], num[w]);
        }
    float inv = 1.f/den;
    uint4 o;
    o.x = pack_bf2(num[0]*inv, num[1]*inv);
    o.y = pack_bf2(num[2]*inv, num[3]*inv);
    o.z = pack_bf2(num[4]*inv, num[5]*inv);
    o.w = pack_bf2(num[6]*inv, num[7]*inv);
    *(uint4*)(Oc + (size_t)tok*64 + h*8) = o;
}

// ---------------- shared mma helpers ------------------------------------------------
__device__ __forceinline__ void ldsm_x4(unsigned& r0, unsigned& r1, unsigned& r2,
                                        unsigned& r3, unsigned addr) {
    asm volatile("ldmatrix.sync.aligned.m8n8.x4.shared.b16 {%0,%1,%2,%3}, [%4];"
                 : "=r"(r0), "=r"(r1), "=r"(r2), "=r"(r3) : "r"(addr));
}
__device__ __forceinline__ void mma16816(float* d, unsigned a0, unsigned a1,
                                         unsigned a2, unsigned a3,
                                         unsigned b0, unsigned b1) {
    asm volatile("mma.sync.aligned.m16n8k16.row.col.f32.bf16.bf16.f32 "
        "{%0,%1,%2,%3}, {%4,%5,%6,%7}, {%8,%9}, {%0,%1,%2,%3};"
        : "+f"(d[0]), "+f"(d[1]), "+f"(d[2]), "+f"(d[3])
        : "r"(a0), "r"(a1), "r"(a2), "r"(a3), "r"(b0), "r"(b1));
}

// ---------------- bf16 mma.sync NT GEMM, 3-stage, fp32 or bf16 output --------------
#define SROW 40
#define GSTAGES 3
#define GSMEM (GSTAGES*2*128*SROW*2)
__device__ __forceinline__ void cp_stage(
    const __nv_bfloat16* A, const __nv_bfloat16* B, int K, int m0, int n0,
    int tid, unsigned asb, unsigned bsb, unsigned stageB, int kt, int buf)
{
    #pragma unroll
    for (int half = 0; half < 2; half++) {
        int s = tid + half*256;
        int r = s >> 2, cch = s & 3;
        const __nv_bfloat16* ga = A + (size_t)(m0+r)*K + kt*32 + cch*8;
        unsigned sa = asb + (unsigned)buf*stageB + (unsigned)(r*SROW + cch*8)*2u;
        asm volatile("cp.async.cg.shared.global [%0], [%1], 16;" :: "r"(sa), "l"(ga));
        const __nv_bfloat16* gb = B + (size_t)(n0+r)*K + kt*32 + cch*8;
        unsigned sb = bsb + (unsigned)buf*stageB + (unsigned)(r*SROW + cch*8)*2u;
        asm volatile("cp.async.cg.shared.global [%0], [%1], 16;" :: "r"(sb), "l"(gb));
    }
    asm volatile("cp.async.commit_group;");
}
__global__ __launch_bounds__(256) void gemm_bf16(
    const __nv_bfloat16* __restrict__ A, const __nv_bfloat16* __restrict__ B,
    float* __restrict__ Cf, __nv_bfloat16* __restrict__ Cb, int K, int N,
    const float* __restrict__ bias, int pe)
{
    extern __shared__ __nv_bfloat16 smem[];
    const int tid  = threadIdx.x;
    const int lane = tid & 31, warp = tid >> 5;
    const int wm = warp & 3, wn = warp >> 2;
    const int m0 = blockIdx.y*128, n0 = blockIdx.x*128;

    const unsigned asb = (unsigned)__cvta_generic_to_shared(smem);
    const unsigned bsb = asb + GSTAGES*128*SROW*2;
    const unsigned stageB = 128*SROW*2;

    float acc[2][8][4];
    #pragma unroll
    for (int i=0;i<2;i++)
        #pragma unroll
        for (int j=0;j<8;j++)
            #pragma unroll
            for (int q=0;q<4;q++) acc[i][j][q]=0.f;

    const int NK = K/32;
    cp_stage(A, B, K, m0, n0, tid, asb, bsb, stageB, 0, 0);
    if (NK > 1) cp_stage(A, B, K, m0, n0, tid, asb, bsb, stageB, 1, 1);

    for (int kt = 0; kt < NK; kt++) {
        const int buf = kt % GSTAGES;
        if (kt + 1 < NK) asm volatile("cp.async.wait_group 1;");
        else             asm volatile("cp.async.wait_group 0;");
        __syncthreads();
        if (kt + 2 < NK)
            cp_stage(A, B, K, m0, n0, tid, asb, bsb, stageB, kt+2, (kt+2)%GSTAGES);

        #pragma unroll
        for (int kk = 0; kk < 2; kk++) {
            unsigned a[2][4];
            #pragma unroll
            for (int mt = 0; mt < 2; mt++) {
                int r = lane & 15, kh = lane >> 4;
                unsigned addr = asb + (unsigned)buf*stageB +
                    (unsigned)((wm*32 + mt*16 + r)*SROW + kk*16 + kh*8)*2u;
                ldsm_x4(a[mt][0], a[mt][1], a[mt][2], a[mt][3], addr);
            }
            unsigned b[8][2];
            #pragma unroll
            for (int p = 0; p < 4; p++) {
                int n  = wn*64 + p*16 + ((lane >> 4) & 1)*8 + (lane & 7);
                int kh = (lane >> 3) & 1;
                unsigned addr = bsb + (unsigned)buf*stageB +
                    (unsigned)(n*SROW + kk*16 + kh*8)*2u;
                ldsm_x4(b[2*p][0], b[2*p][1], b[2*p+1][0], b[2*p+1][1], addr);
            }
            #pragma unroll
            for (int mt = 0; mt < 2; mt++)
                #pragma unroll
                for (int nt = 0; nt < 8; nt++)
                    mma16816(acc[mt][nt], a[mt][0], a[mt][1], a[mt][2], a[mt][3],
                             b[nt][0], b[nt][1]);
        }
        __syncthreads();
    }

    #pragma unroll
    for (int mt = 0; mt < 2; mt++) {
        int row = m0 + wm*32 + mt*16 + (lane >> 2);
        int s = row & (SEQ-1);
        #pragma unroll
        for (int nt = 0; nt < 8; nt++) {
            int col = n0 + wn*64 + nt*8 + (lane & 3)*2;
            float2 v0 = make_float2(acc[mt][nt][0], acc[mt][nt][1]);
            float2 v1 = make_float2(acc[mt][nt][2], acc[mt][nt][3]);
            if (bias) {
                v0.x += bias[col]; v0.y += bias[col+1];
                v1.x += bias[col]; v1.y += bias[col+1];
            }
            if (pe) {
                v0.x += g_pe[(size_t)s*EMBED + col];
                v0.y += g_pe[(size_t)s*EMBED + col + 1];
                v1.x += g_pe[(size_t)(s+8)*EMBED + col];
                v1.y += g_pe[(size_t)(s+8)*EMBED + col + 1];
            }
            if (Cb) {
                *(unsigned*)(Cb + (size_t)row*N + col)     = pack_bf2(v0.x, v0.y);
                *(unsigned*)(Cb + (size_t)(row+8)*N + col) = pack_bf2(v1.x, v1.y);
            } else {
                *(float2*)(Cf + (size_t)row*N + col)     = v0;
                *(float2*)(Cf + (size_t)(row+8)*N + col) = v1;
            }
        }
    }
}

// ============ fused Wo-GEMM + residual + LayerNorm (32 tok x 512) ==================
#define WROW 72
#define WO_SMEM (512*WROW*2 + 32*WROW*2 + 2048 + 256)
__global__ __launch_bounds__(256) void gemm_wo_ln(
    const __nv_bfloat16* __restrict__ Oc, const __nv_bfloat16* __restrict__ U,
    const float* __restrict__ gg, const float* __restrict__ bb)
{
    extern __shared__ char ds[];
    const unsigned bsb = (unsigned)__cvta_generic_to_shared(ds);
    const unsigned asb = bsb + 512*WROW*2;
    float* part_s = (float*)(ds + 512*WROW*2 + 32*WROW*2);
    float* part_q = part_s + 256;
    float2* stats = (float2*)(part_q + 256);

    const int tid = threadIdx.x, lane = tid & 31, w = tid >> 5;
    const int t0 = blockIdx.x*32;

    #pragma unroll
    for (int i = 0; i < 16; i++) {
        int s = tid + i*256;
        int r = s >> 3, ch = s & 7;
        unsigned sa = bsb + (unsigned)(r*WROW + ch*8)*2u;
        asm volatile("cp.async.cg.shared.global [%0], [%1], 16;"
                     :: "r"(sa), "l"(U + (size_t)r*64 + ch*8));
    }
    {
        int r = tid >> 3, ch = tid & 7;
        unsigned sa = asb + (unsigned)(r*WROW + ch*8)*2u;
        asm volatile("cp.async.cg.shared.global [%0], [%1], 16;"
                     :: "r"(sa), "l"(Oc + (size_t)(t0+r)*64 + ch*8));
    }
    asm volatile("cp.async.commit_group;");
    asm volatile("cp.async.wait_group 0;");
    __syncthreads();

    float acc[2][8][4];
    #pragma unroll
    for (int i=0;i<2;i++)
        #pragma unroll
        for (int j=0;j<8;j++)
            #pragma unroll
            for (int q=0;q<4;q++) acc[i][j][q]=0.f;

    #pragma unroll
    for (int kk = 0; kk < 4; kk++) {
        unsigned a[2][4];
        #pragma unroll
        for (int mt = 0; mt < 2; mt++) {
            int r = lane & 15, kh = lane >> 4;
            unsigned addr = asb + (unsigned)((mt*16 + r)*WROW + kk*16 + kh*8)*2u;
            ldsm_x4(a[mt][0], a[mt][1], a[mt][2], a[mt][3], addr);
        }
        unsigned b[8][2];
        #pragma unroll
        for (int p = 0; p < 4; p++) {
            int n  = w*64 + p*16 + ((lane >> 4) & 1)*8 + (lane & 7);
            int kh = (lane >> 3) & 1;
            unsigned addr = bsb + (unsigned)(n*WROW + kk*16 + kh*8)*2u;
            ldsm_x4(b[2*p][0], b[2*p][1], b[2*p+1][0], b[2*p+1][1], addr);
        }
        #pragma unroll
        for (int mt = 0; mt < 2; mt++)
            #pragma unroll
            for (int nt = 0; nt < 8; nt++)
                mma16816(acc[mt][nt], a[mt][0], a[mt][1], a[mt][2], a[mt][3],
                         b[nt][0], b[nt][1]);
    }

    float sum[2][2] = {{0.f,0.f},{0.f,0.f}};
    float sq [2][2] = {{0.f,0.f},{0.f,0.f}};
    #pragma unroll
    for (int mt = 0; mt < 2; mt++) {
        int row = mt*16 + (lane >> 2);
        #pragma unroll
        for (int nt = 0; nt < 8; nt++) {
            int col = w*64 + nt*8 + (lane & 3)*2;
            float2 h0 = *(const float2*)(g_h + (size_t)(t0+row)*EMBED + col);
            float2 h1 = *(const float2*)(g_h + (size_t)(t0+row+8)*EMBED + col);
            acc[mt][nt][0] += h0.x; acc[mt][nt][1] += h0.y;
            acc[mt][nt][2] += h1.x; acc[mt][nt][3] += h1.y;
            sum[mt][0] += acc[mt][nt][0] + acc[mt][nt][1];
            sum[mt][1] += acc[mt][nt][2] + acc[mt][nt][3];
            sq[mt][0]  += acc[mt][nt][0]*acc[mt][nt][0] + acc[mt][nt][1]*acc[mt][nt][1];
            sq[mt][1]  += acc[mt][nt][2]*acc[mt][nt][2] + acc[mt][nt][3]*acc[mt][nt][3];
        }
    }
    #pragma unroll
    for (int o = 1; o < 4; o <<= 1) {
        #pragma unroll
        for (int mt = 0; mt < 2; mt++)
            #pragma unroll
            for (int hf = 0; hf < 2; hf++) {
                sum[mt][hf] += __shfl_xor_sync(0xffffffffu, sum[mt][hf], o);
                sq[mt][hf]  += __shfl_xor_sync(0xffffffffu, sq[mt][hf], o);
            }
    }
    if ((lane & 3) == 0) {
        int r0 = lane >> 2;
        #pragma unroll
        for (int mt = 0; mt < 2; mt++)
            #pragma unroll
            for (int hf = 0; hf < 2; hf++) {
                int row = mt*16 + hf*8 + r0;
                part_s[row*8 + w] = sum[mt][hf];
                part_q[row*8 + w] = sq[mt][hf];
            }
    }
    __syncthreads();
    {
        int row = tid >> 3;
        float s1 = part_s[tid], s2 = part_q[tid];
        #pragma unroll
        for (int o = 1; o < 8; o <<= 1) {
            s1 += __shfl_xor_sync(0xffffffffu, s1, o);
            s2 += __shfl_xor_sync(0xffffffffu, s2, o);
        }
        if ((tid & 7) == 0) {
            float mu  = s1 * (1.f/EMBED);
            float var = s2 * (1.f/EMBED) - mu*mu;
            stats[row] = make_float2(mu, rsqrtf(var + 1e-5f));
        }
    }
    __syncthreads();
    #pragma unroll
    for (int mt = 0; mt < 2; mt++) {
        int row = mt*16 + (lane >> 2);
        float2 s0 = stats[row], s1 = stats[row+8];
        #pragma unroll
        for (int nt = 0; nt < 8; nt++) {
            int col = w*64 + nt*8 + (lane & 3)*2;
            float2 gv = *(const float2*)(gg + col);
            float2 bv = *(const float2*)(bb + col);
            float2 o0, o1;
            o0.x = (acc[mt][nt][0] - s0.x)*s0.y*gv.x + bv.x;
            o0.y = (acc[mt][nt][1] - s0.x)*s0.y*gv.y + bv.y;
            o1.x = (acc[mt][nt][2] - s1.x)*s1.y*gv.x + bv.x;
            o1.y = (acc[mt][nt][3] - s1.x)*s1.y*gv.y + bv.y;
            *(float2*)(g_h + (size_t)(t0+row)*EMBED + col)   = o0;
            *(float2*)(g_h + (size_t)(t0+row+8)*EMBED + col) = o1;
        }
    }
}

// ---------------- rank-8 FFN hidden, 16 tokens/CTA -> bf16 -------------------------
__global__ __launch_bounds__(256) void ffn1_kernel(const float* __restrict__ phi,
                                                   const float* __restrict__ W1) {
    __shared__ float cs[16*8];
    const int tid = threadIdx.x;
    const int t0 = blockIdx.x*16;
    if (tid < 128) {
        int tok = tid >> 3, w = tid & 7;
        cs[tid] = cosf(g_h[(size_t)(t0+tok)*EMBED + w] + phi[w]);
    }
    __syncthreads();
    #pragma unroll
    for (int it = 0; it < 8; it++) {
        int j = tid + it*256;
        const float4* w4 = (const float4*)(W1 + (size_t)j*NW);
        float4 w0 = w4[0], w1 = w4[1];
        #pragma unroll
        for (int tok = 0; tok < 16; tok++) {
            const float* c = cs + tok*8;
            float a = c[0]*w0.x + c[1]*w0.y + c[2]*w0.z + c[3]*w0.w
                    + c[4]*w1.x + c[5]*w1.y + c[6]*w1.z + c[7]*w1.w;
            g_fb[(size_t)(t0+tok)*FFN_ + j] = __float2bfloat16(fmaxf(a, 0.f));
        }
    }
}

// ---------------- residual + layernorm (post-W2; tmp in bf16) ----------------------
__global__ __launch_bounds__(128) void addln_kernel(const float* __restrict__ gg,
                                                    const float* __restrict__ bb) {
    int t = blockIdx.x;
    int tid = threadIdx.x;
    __shared__ float r1[4], r2[4];
    float v[4]; float s = 0.f;
    #pragma unroll
    for (int q=0;q<4;q++) {
        int e = tid + q*128;
        float val = g_h[(size_t)t*EMBED+e] + __bfloat162float(g_tmpb[(size_t)t*EMBED+e]);
        v[q]=val; s+=val;
    }
    #pragma unroll
    for (int o=16;o;o>>=1) s += __shfl_down_sync(0xffffffffu, s, o);
    if ((tid&31)==0) r1[tid>>5]=s;
    __syncthreads();
    float mu = (r1[0]+r1[1]+r1[2]+r1[3]) * (1.f/EMBED);
    float vs = 0.f;
    #pragma unroll
    for (int q=0;q<4;q++) { float d=v[q]-mu; vs += d*d; }
    #pragma unroll
    for (int o=16;o;o>>=1) vs += __shfl_down_sync(0xffffffffu, vs, o);
    if ((tid&31)==0) r2[tid>>5]=vs;
    __syncthreads();
    float var = (r2[0]+r2[1]+r2[2]+r2[3]) * (1.f/EMBED);
    float inv = rsqrtf(var + 1e-5f);
    #pragma unroll
    for (int q=0;q<4;q++) {
        int e = tid + q*128;
        g_h[(size_t)t*EMBED+e] = (v[q]-mu)*inv*gg[e] + bb[e];
    }
}

// ---------------- mean pool, 2-phase -----------------------------------------------
__global__ void pool1_kernel() {
    int ch = blockIdx.x, b = blockIdx.y, e = threadIdx.x;
    float s = 0.f;
    #pragma unroll 4
    for (int i = 0; i < 128; i++)
        s += g_h[((size_t)b*SEQ + ch*128 + i)*EMBED + e];
    g_poolp[((size_t)b*16 + ch)*EMBED + e] = s;
}
__global__ void pool2_kernel() {
    int b = blockIdx.x, e = threadIdx.x;
    float s = 0.f;
    #pragma unroll
    for (int ch = 0; ch < 16; ch++)
        s += g_poolp[((size_t)b*16 + ch)*EMBED + e];
    g_pool[b*EMBED + e] = s * (1.f/SEQ);
}

// ---------------- classifier -------------------------------------------------------
__global__ void cls_kernel(const float* __restrict__ Wc, const float* __restrict__ bc,
                           float* __restrict__ out) {
    int idx = blockIdx.x*blockDim.x + threadIdx.x;
    if (idx >= BATCH*CLASSES) return;
    int b = idx / CLASSES, c = idx % CLASSES;
    const float* p = g_pool + b*EMBED;
    const float* w = Wc + (size_t)c*EMBED;
    float s = bc[c];
    for (int e=0;e<EMBED;e++) s = fmaf(p[e], w[e], s);
    out[idx] = s;
}

// ---------------- launch -----------------------------------------------------------
extern "C" void kernel_launch(void* const* d_in, const int* in_sizes, int n_in,
                              void* d_out, int out_size) {
    const float* x     = (const float*)d_in[0];
    const float* Wi    = (const float*)d_in[1];
    const float* bi    = (const float*)d_in[2];
    const float* theta = (const float*)d_in[3];
    const float* Wproj = (const float*)d_in[4];
    const float* Wq    = (const float*)d_in[5];
    const float* Wk    = (const float*)d_in[6];
    const float* Wv    = (const float*)d_in[7];
    const float* Wo    = (const float*)d_in[8];
    const float* g1    = (const float*)d_in[9];
    const float* b1    = (const float*)d_in[10];
    const float* phi   = (const float*)d_in[11];
    const float* W1    = (const float*)d_in[12];
    const float* W2    = (const float*)d_in[13];
    const float* g2    = (const float*)d_in[14];
    const float* b2    = (const float*)d_in[15];
    const float* Wc    = (const float*)d_in[16];
    const float* bc    = (const float*)d_in[17];
    float* out = (float*)d_out;

    float *p_h, *p_m;
    __nv_bfloat16 *p_tmpb, *p_fb, *p_w2b, *p_ocb, *p_ub, *p_xcat, *p_wcat;
    cudaGetSymbolAddress((void**)&p_h,    g_h);
    cudaGetSymbolAddress((void**)&p_tmpb, g_tmpb);
    cudaGetSymbolAddress((void**)&p_fb,   g_fb);
    cudaGetSymbolAddress((void**)&p_w2b,  g_w2b);
    cudaGetSymbolAddress((void**)&p_ocb,  g_ocb);
    cudaGetSymbolAddress((void**)&p_ub,   g_ub);
    cudaGetSymbolAddress((void**)&p_m,    g_m);
    cudaGetSymbolAddress((void**)&p_xcat, g_xcat);
    cudaGetSymbolAddress((void**)&p_wcat, g_wcat);

    cudaFuncSetAttribute(gemm_bf16, cudaFuncAttributeMaxDynamicSharedMemorySize, GSMEM);
    cudaFuncSetAttribute(gemm_wo_ln, cudaFuncAttributeMaxDynamicSharedMemorySize, WO_SMEM);

    setup1_kernel<<<SB_EFF, 256>>>(x, Wi, W2, Wq, Wk, Wv, Wproj);
    setup2_kernel<<<130, 512>>>(Wo);

    dim3 gg(EMBED/128, TOK/128);   // (4, 128)
    gemm_bf16<<<gg, 256, GSMEM>>>(p_xcat, p_wcat, p_h, nullptr, 768, EMBED, bi, 1);

    for (int l = 0; l < 2; l++) {
        stats_kernel<<<dim3(9, BATCH, 4), 256>>>(theta + l*NW);
        eval_kernel<<<TOK/32, 256>>>(theta + l*NW, p_m + (size_t)l*HEADS*64, p_ocb);
        gemm_wo_ln<<<TOK/32, 256, WO_SMEM>>>(p_ocb, p_ub + (size_t)l*EMBED*64,
                                             g1 + l*EMBED, b1 + l*EMBED);
        ffn1_kernel<<<TOK/16, 256>>>(phi + l*NW, W1 + (size_t)l*FFN_*NW);
        gemm_bf16<<<gg, 256, GSMEM>>>(p_fb, p_w2b + (size_t)l*EMBED*FFN_,
                                      nullptr, p_tmpb, FFN_, EMBED, nullptr, 0);
        addln_kernel<<<TOK, 128>>>(g2 + l*EMBED, b2 + l*EMBED);
    }

    pool1_kernel<<<dim3(16, BATCH), EMBED>>>();
    pool2_kernel<<<BATCH, EMBED>>>();
    cls_kernel<<<(BATCH*CLASSES + 255)/256, 256>>>(Wc, bc, out);
}

// round 14
// speedup vs baseline: 1.2699x; 1.0672x over previous
#include <cuda_runtime.h>
#include <cuda_bf16.h>
#include <cstdint>
#include <cstdio>
#include <math.h>

#define BATCH   8
#define SEQ     2048
#define TOK     (BATCH*SEQ)      // 16384
#define INF_    256
#define EMBED   512
#define HEADS   8
#define HD      64
#define FFN_    2048
#define NW      8
#define CLASSES 1000

// ---------------- scratch (device globals: allocation-free contract) ----------------
__device__ float g_h[TOK*EMBED];              // residual stream (fp32)
__device__ __nv_bfloat16 g_tmpb[TOK*EMBED];   // ffn_out (bf16)
__device__ __nv_bfloat16 g_fb[TOK*FFN_];      // FFN hidden (relu'd, bf16)
__device__ __nv_bfloat16 g_w2b[2*EMBED*FFN_]; // W2 in bf16
__device__ __nv_bfloat16 g_ub[2*EMBED*64];    // U in bf16
__device__ __nv_bfloat16 g_xcat[TOK*768];     // [xh | xh | xl]
__device__ __nv_bfloat16 g_wcat[EMBED*768];   // [wih | wil | wih]
__device__ float g_weff[2*3*EMBED*NW];
__device__ float g_m[2*HEADS*NW*NW];
__device__ float g_Tp[4][BATCH*512];          // moment partials (4 chunks)
__device__ float g_Gp[4][BATCH*64];
__device__ float g_S0p[4][BATCH*8];
__device__ float g_pool[BATCH*EMBED];
__device__ float g_poolp[BATCH*16*EMBED];
__device__ float g_pe[SEQ*EMBED];

__device__ __forceinline__ unsigned pack_bf2(float lo, float hi) {
    __nv_bfloat162 v = __float22bfloat162_rn(make_float2(lo, hi));
    return *(unsigned*)&v;
}

// ================= fat setup kernel 1: pe | splitx | splitw | w2b | eff ============
// pe: 64 blocks, each thread owns column pair (2j,2j+1) for a 32-row chunk;
// fp64 anchor + fp32 incremental rotation (drift <= ~3e-6, far under budget).
#define SB_PE    64
#define SB_SX    (SB_PE + 16384)
#define SB_SW    (SB_SX + 512)
#define SB_W2    (SB_SW + 8192)
#define SB_EFF   (SB_W2 + 192)
__global__ __launch_bounds__(256) void setup1_kernel(
    const float* __restrict__ x, const float* __restrict__ Wi,
    const float* __restrict__ W2,
    const float* __restrict__ Wq, const float* __restrict__ Wk,
    const float* __restrict__ Wv, const float* __restrict__ Wp)
{
    int blk = blockIdx.x, tid = threadIdx.x;
    if (blk < SB_PE) {
        int j = tid;                     // column pair
        int s0 = blk*32;
        double div = exp(-(double)(2*j) * log(10000.0) / (double)EMBED);
        double ang = fmod((double)s0 * div, 6.283185307179586476925286766559);
        float sn = (float)sin(ang), cn = (float)cos(ang);
        float ds = (float)sin(div), dc = (float)cos(div);
        float* base = g_pe + (size_t)s0*EMBED;
        #pragma unroll 4
        for (int i = 0; i < 32; i++) {
            base[(size_t)i*EMBED + 2*j]     = sn;
            base[(size_t)i*EMBED + 2*j + 1] = cn;
            float ns = sn*dc + cn*ds;
            float nc = cn*dc - sn*ds;
            sn = ns; cn = nc;
        }
    } else if (blk < SB_SX) {
        int i = (blk - SB_PE)*256 + tid;
        int t = i / INF_, k = i % INF_;
        float v = x[i];
        __nv_bfloat16 h = __float2bfloat16(v);
        __nv_bfloat16 l = __float2bfloat16(v - __bfloat162float(h));
        size_t b = (size_t)t*768 + k;
        g_xcat[b] = h; g_xcat[b+256] = h; g_xcat[b+512] = l;
    } else if (blk < SB_SW) {
        int i = (blk - SB_SX)*256 + tid;
        int n = i / INF_, k = i % INF_;
        float v = Wi[i];
        __nv_bfloat16 h = __float2bfloat16(v);
        __nv_bfloat16 l = __float2bfloat16(v - __bfloat162float(h));
        size_t b = (size_t)n*768 + k;
        g_wcat[b] = h; g_wcat[b+256] = l; g_wcat[b+512] = h;
    } else if (blk < SB_W2) {
        int i = (blk - SB_SW)*256 + tid;
        g_w2b[i] = __float2bfloat16(W2[i]);
    } else {
        int idx = (blk - SB_W2)*256 + tid;
        int l   = idx / (3*EMBED*NW);
        int r   = idx % (3*EMBED*NW);
        int mat = r / (EMBED*NW);
        int r2  = r % (EMBED*NW);
        int f   = r2 / NW;
        int w   = r2 % NW;
        const float* W = (mat==0 ? Wq : (mat==1 ? Wk : Wv)) + (size_t)l*EMBED*EMBED + (size_t)f*EMBED;
        const float* P = Wp + (size_t)l*EMBED*NW + w;
        float s = 0.f;
        for (int e = 0; e < EMBED; e++) s = fmaf(W[e], P[(size_t)e*NW], s);
        g_weff[idx] = s;
    }
}

// ================= fat setup kernel 2: mh | u ======================================
__global__ __launch_bounds__(512) void setup2_kernel(const float* __restrict__ Wo) {
    int blk = blockIdx.x, tid = threadIdx.x;
    if (blk < 2) {
        int l = blk;
        int h = tid >> 6, uv = tid & 63, u = uv >> 3, v = uv & 7;
        const float* Wq = g_weff + ((size_t)(l*3+0)*EMBED + h*HD)*NW;
        const float* Wk = g_weff + ((size_t)(l*3+1)*EMBED + h*HD)*NW;
        float s = 0.f;
        for (int d = 0; d < HD; d++) s = fmaf(Wq[d*NW + u], Wk[d*NW + v], s);
        g_m[((size_t)l*HEADS + h)*64 + u*8 + v] = s;
    } else {
        int idx = (blk - 2)*512 + tid;
        int l = idx / (EMBED*64);
        int f = (idx / 64) % EMBED;
        int e = idx % 64;
        int h = e >> 3, w = e & 7;
        const float* wo = Wo + ((size_t)l*EMBED + f)*EMBED + h*HD;
        const float* wv = g_weff + ((size_t)(l*3+2)*EMBED + h*HD)*NW + w;
        float s = 0.f;
        for (int d = 0; d < HD; d++) s = fmaf(wo[d], wv[(size_t)d*NW], s);
        g_ub[idx] = __float2bfloat16(s);
    }
}

// ================= attention moment statistics (4-way chunked) =====================
__global__ __launch_bounds__(256) void stats_kernel(const float* __restrict__ theta) {
    const int wsel = blockIdx.x;
    const int b = blockIdx.y;
    const int z = blockIdx.z;
    const int tid = threadIdx.x, lane = tid & 31, wp = tid >> 5;
    __shared__ float red[8*65];
    float acc[64];
    #pragma unroll
    for (int i = 0; i < 64; i++) acc[i] = 0.f;
    float s0 = 0.f;
    float th[8];
    #pragma unroll
    for (int u = 0; u < 8; u++) th[u] = theta[u];

    for (int i = 0; i < 2; i++) {
        int k = b*SEQ + z*512 + i*256 + tid;
        float c[8];
        #pragma unroll
        for (int u = 0; u < 8; u++)
            c[u] = cosf(g_h[(size_t)k*EMBED + u] + th[u]);
        float mult = (wsel < 8) ? c[wsel] : 1.f;
        s0 += mult;
        float mc[8];
        #pragma unroll
        for (int u = 0; u < 8; u++) mc[u] = mult*c[u];
        #pragma unroll
        for (int u = 0; u < 8; u++)
            #pragma unroll
            for (int v = 0; v < 8; v++)
                acc[u*8+v] = fmaf(mc[u], c[v], acc[u*8+v]);
    }
    #pragma unroll
    for (int o = 16; o; o >>= 1) {
        #pragma unroll
        for (int i = 0; i < 64; i++) acc[i] += __shfl_xor_sync(0xffffffffu, acc[i], o);
        s0 += __shfl_xor_sync(0xffffffffu, s0, o);
    }
    if (lane == 0) {
        #pragma unroll
        for (int i = 0; i < 64; i++) red[wp*65 + i] = acc[i];
        red[wp*65 + 64] = s0;
    }
    __syncthreads();
    if (tid < 64) {
        float s = 0.f;
        #pragma unroll
        for (int w2 = 0; w2 < 8; w2++) s += red[w2*65 + tid];
        if (wsel < 8) g_Tp[z][b*512 + tid*8 + wsel] = s;
        else          g_Gp[z][b*64 + tid] = s;
    }
    if (tid == 64 && wsel < 8) {
        float s = 0.f;
        #pragma unroll
        for (int w2 = 0; w2 < 8; w2++) s += red[w2*65 + 64];
        g_S0p[z][b*8 + wsel] = s;
    }
}

// ---------------- shared mma helpers ------------------------------------------------
__device__ __forceinline__ void ldsm_x4(unsigned& r0, unsigned& r1, unsigned& r2,
                                        unsigned& r3, unsigned addr) {
    asm volatile("ldmatrix.sync.aligned.m8n8.x4.shared.b16 {%0,%1,%2,%3}, [%4];"
                 : "=r"(r0), "=r"(r1), "=r"(r2), "=r"(r3) : "r"(addr));
}
__device__ __forceinline__ void mma16816(float* d, unsigned a0, unsigned a1,
                                         unsigned a2, unsigned a3,
                                         unsigned b0, unsigned b1) {
    asm volatile("mma.sync.aligned.m16n8k16.row.col.f32.bf16.bf16.f32 "
        "{%0,%1,%2,%3}, {%4,%5,%6,%7}, {%8,%9}, {%0,%1,%2,%3};"
        : "+f"(d[0]), "+f"(d[1]), "+f"(d[2]), "+f"(d[3])
        : "r"(a0), "r"(a1), "r"(a2), "r"(a3), "r"(b0), "r"(b1));
}

// ---------------- bf16 mma.sync NT GEMM, 3-stage, fp32 or bf16 output --------------
#define SROW 40
#define GSTAGES 3
#define GSMEM (GSTAGES*2*128*SROW*2)
__device__ __forceinline__ void cp_stage(
    const __nv_bfloat16* A, const __nv_bfloat16* B, int K, int m0, int n0,
    int tid, unsigned asb, unsigned bsb, unsigned stageB, int kt, int buf)
{
    #pragma unroll
    for (int half = 0; half < 2; half++) {
        int s = tid + half*256;
        int r = s >> 2, cch = s & 3;
        const __nv_bfloat16* ga = A + (size_t)(m0+r)*K + kt*32 + cch*8;
        unsigned sa = asb + (unsigned)buf*stageB + (unsigned)(r*SROW + cch*8)*2u;
        asm volatile("cp.async.cg.shared.global [%0], [%1], 16;" :: "r"(sa), "l"(ga));
        const __nv_bfloat16* gb = B + (size_t)(n0+r)*K + kt*32 + cch*8;
        unsigned sb = bsb + (unsigned)buf*stageB + (unsigned)(r*SROW + cch*8)*2u;
        asm volatile("cp.async.cg.shared.global [%0], [%1], 16;" :: "r"(sb), "l"(gb));
    }
    asm volatile("cp.async.commit_group;");
}
__global__ __launch_bounds__(256) void gemm_bf16(
    const __nv_bfloat16* __restrict__ A, const __nv_bfloat16* __restrict__ B,
    float* __restrict__ Cf, __nv_bfloat16* __restrict__ Cb, int K, int N,
    const float* __restrict__ bias, int pe)
{
    extern __shared__ __nv_bfloat16 smem[];
    const int tid  = threadIdx.x;
    const int lane = tid & 31, warp = tid >> 5;
    const int wm = warp & 3, wn = warp >> 2;
    const int m0 = blockIdx.y*128, n0 = blockIdx.x*128;

    const unsigned asb = (unsigned)__cvta_generic_to_shared(smem);
    const unsigned bsb = asb + GSTAGES*128*SROW*2;
    const unsigned stageB = 128*SROW*2;

    float acc[2][8][4];
    #pragma unroll
    for (int i=0;i<2;i++)
        #pragma unroll
        for (int j=0;j<8;j++)
            #pragma unroll
            for (int q=0;q<4;q++) acc[i][j][q]=0.f;

    const int NK = K/32;
    cp_stage(A, B, K, m0, n0, tid, asb, bsb, stageB, 0, 0);
    if (NK > 1) cp_stage(A, B, K, m0, n0, tid, asb, bsb, stageB, 1, 1);

    for (int kt = 0; kt < NK; kt++) {
        const int buf = kt % GSTAGES;
        if (kt + 1 < NK) asm volatile("cp.async.wait_group 1;");
        else             asm volatile("cp.async.wait_group 0;");
        __syncthreads();
        if (kt + 2 < NK)
            cp_stage(A, B, K, m0, n0, tid, asb, bsb, stageB, kt+2, (kt+2)%GSTAGES);

        #pragma unroll
        for (int kk = 0; kk < 2; kk++) {
            unsigned a[2][4];
            #pragma unroll
            for (int mt = 0; mt < 2; mt++) {
                int r = lane & 15, kh = lane >> 4;
                unsigned addr = asb + (unsigned)buf*stageB +
                    (unsigned)((wm*32 + mt*16 + r)*SROW + kk*16 + kh*8)*2u;
                ldsm_x4(a[mt][0], a[mt][1], a[mt][2], a[mt][3], addr);
            }
            unsigned b[8][2];
            #pragma unroll
            for (int p = 0; p < 4; p++) {
                int n  = wn*64 + p*16 + ((lane >> 4) & 1)*8 + (lane & 7);
                int kh = (lane >> 3) & 1;
                unsigned addr = bsb + (unsigned)buf*stageB +
                    (unsigned)(n*SROW + kk*16 + kh*8)*2u;
                ldsm_x4(b[2*p][0], b[2*p][1], b[2*p+1][0], b[2*p+1][1], addr);
            }
            #pragma unroll
            for (int mt = 0; mt < 2; mt++)
                #pragma unroll
                for (int nt = 0; nt < 8; nt++)
                    mma16816(acc[mt][nt], a[mt][0], a[mt][1], a[mt][2], a[mt][3],
                             b[nt][0], b[nt][1]);
        }
        __syncthreads();
    }

    #pragma unroll
    for (int mt = 0; mt < 2; mt++) {
        int row = m0 + wm*32 + mt*16 + (lane >> 2);
        int s = row & (SEQ-1);
        #pragma unroll
        for (int nt = 0; nt < 8; nt++) {
            int col = n0 + wn*64 + nt*8 + (lane & 3)*2;
            float2 v0 = make_float2(acc[mt][nt][0], acc[mt][nt][1]);
            float2 v1 = make_float2(acc[mt][nt][2], acc[mt][nt][3]);
            if (bias) {
                v0.x += bias[col]; v0.y += bias[col+1];
                v1.x += bias[col]; v1.y += bias[col+1];
            }
            if (pe) {
                v0.x += g_pe[(size_t)s*EMBED + col];
                v0.y += g_pe[(size_t)s*EMBED + col + 1];
                v1.x += g_pe[(size_t)(s+8)*EMBED + col];
                v1.y += g_pe[(size_t)(s+8)*EMBED + col + 1];
            }
            if (Cb) {
                *(unsigned*)(Cb + (size_t)row*N + col)     = pack_bf2(v0.x, v0.y);
                *(unsigned*)(Cb + (size_t)(row+8)*N + col) = pack_bf2(v1.x, v1.y);
            } else {
                *(float2*)(Cf + (size_t)row*N + col)     = v0;
                *(float2*)(Cf + (size_t)(row+8)*N + col) = v1;
            }
        }
    }
}

// ============ fused eval + Wo-GEMM + residual + LayerNorm (32 tok x 512) ===========
// Prologue computes Oc (series softmax) straight into the A smem tile.
#define WROW 72
#define WO_OFF_A   (512*WROW*2)               // 73728
#define WO_OFF_PS  (WO_OFF_A + 32*WROW*2)     // 78336
#define WO_OFF_PQ  (WO_OFF_PS + 1024)         // 79360
#define WO_OFF_ST  (WO_OFF_PQ + 1024)         // 80384
#define WO_OFF_TS  (WO_OFF_ST + 256)          // 80640
#define WO_OFF_MS  (WO_OFF_TS + 2048)         // 82688
#define WO_OFF_GS  (WO_OFF_MS + 2048)         // 84736
#define WO_OFF_S0  (WO_OFF_GS + 256)          // 84992
#define WO_SMEM    (WO_OFF_S0 + 32)           // 85024
__global__ __launch_bounds__(256) void gemm_wo_ln(
    const float* __restrict__ theta, const float* __restrict__ M,
    const __nv_bfloat16* __restrict__ U,
    const float* __restrict__ gg, const float* __restrict__ bb)
{
    extern __shared__ char ds[];
    const unsigned bsb = (unsigned)__cvta_generic_to_shared(ds);
    const unsigned asb = bsb + WO_OFF_A;
    float* part_s = (float*)(ds + WO_OFF_PS);
    float* part_q = (float*)(ds + WO_OFF_PQ);
    float2* stats = (float2*)(ds + WO_OFF_ST);
    float* Ts  = (float*)(ds + WO_OFF_TS);
    float* Ms  = (float*)(ds + WO_OFF_MS);
    float* Gs  = (float*)(ds + WO_OFF_GS);
    float* S0s = (float*)(ds + WO_OFF_S0);

    const int tid = threadIdx.x, lane = tid & 31, w = tid >> 5;
    const int t0 = blockIdx.x*32;
    const int b = t0 >> 11;

    // stage U (512x64) via cp.async (overlaps the eval prologue)
    #pragma unroll
    for (int i = 0; i < 16; i++) {
        int s = tid + i*256;
        int r = s >> 3, ch = s & 7;
        unsigned sa = bsb + (unsigned)(r*WROW + ch*8)*2u;
        asm volatile("cp.async.cg.shared.global [%0], [%1], 16;"
                     :: "r"(sa), "l"(U + (size_t)r*64 + ch*8));
    }
    asm volatile("cp.async.commit_group;");

    // stage moments + M
    Ts[tid]     = g_Tp[0][b*512+tid]     + g_Tp[1][b*512+tid]
                + g_Tp[2][b*512+tid]     + g_Tp[3][b*512+tid];
    Ts[tid+256] = g_Tp[0][b*512+256+tid] + g_Tp[1][b*512+256+tid]
                + g_Tp[2][b*512+256+tid] + g_Tp[3][b*512+256+tid];
    Ms[tid] = M[tid];           Ms[tid+256] = M[tid+256];
    if (tid < 64) Gs[tid] = g_Gp[0][b*64+tid] + g_Gp[1][b*64+tid]
                          + g_Gp[2][b*64+tid] + g_Gp[3][b*64+tid];
    if (tid < 8)  S0s[tid] = g_S0p[0][b*8+tid] + g_S0p[1][b*8+tid]
                           + g_S0p[2][b*8+tid] + g_S0p[3][b*8+tid];
    __syncthreads();

    // eval: thread (tok = tid>>3, h = tid&7) -> 8 bf16 into A smem tile
    {
        const int tokl = tid >> 3;
        const int tok = t0 + tokl;
        const int h = tid & 7;
        float c[8];
        #pragma unroll
        for (int u = 0; u < 8; u++)
            c[u] = cosf(g_h[(size_t)tok*EMBED + u] + theta[u]);
        float a[8];
        #pragma unroll
        for (int v = 0; v < 8; v++) {
            float s = 0.f;
            #pragma unroll
            for (int u = 0; u < 8; u++) s = fmaf(c[u], Ms[h*64 + u*8 + v], s);
            a[v] = 0.125f*s;
        }
        float num[8];
        float den = (float)SEQ;
        #pragma unroll
        for (int ww = 0; ww < 8; ww++) num[ww] = S0s[ww];
        #pragma unroll
        for (int u = 0; u < 8; u++) {
            den = fmaf(a[u], S0s[u], den);
            #pragma unroll
            for (int ww = 0; ww < 8; ww++) num[ww] = fmaf(a[u], Gs[u*8+ww], num[ww]);
        }
        #pragma unroll
        for (int u = 0; u < 8; u++)
            #pragma unroll
            for (int v = 0; v < 8; v++) {
                float q = 0.5f*a[u]*a[v];
                den = fmaf(q, Gs[u*8+v], den);
                #pragma unroll
                for (int ww = 0; ww < 8; ww++)
                    num[ww] = fmaf(q, Ts[(u*8+v)*8 + ww], num[ww]);
            }
        float inv = 1.f/den;
        uint4 o;
        o.x = pack_bf2(num[0]*inv, num[1]*inv);
        o.y = pack_bf2(num[2]*inv, num[3]*inv);
        o.z = pack_bf2(num[4]*inv, num[5]*inv);
        o.w = pack_bf2(num[6]*inv, num[7]*inv);
        *(uint4*)(ds + WO_OFF_A + (unsigned)(tokl*WROW + h*8)*2u) = o;
    }
    asm volatile("cp.async.wait_group 0;");
    __syncthreads();

    float acc[2][8][4];
    #pragma unroll
    for (int i=0;i<2;i++)
        #pragma unroll
        for (int j=0;j<8;j++)
            #pragma unroll
            for (int q=0;q<4;q++) acc[i][j][q]=0.f;

    #pragma unroll
    for (int kk = 0; kk < 4; kk++) {
        unsigned a[2][4];
        #pragma unroll
        for (int mt = 0; mt < 2; mt++) {
            int r = lane & 15, kh = lane >> 4;
            unsigned addr = asb + (unsigned)((mt*16 + r)*WROW + kk*16 + kh*8)*2u;
            ldsm_x4(a[mt][0], a[mt][1], a[mt][2], a[mt][3], addr);
        }
        unsigned b2[8][2];
        #pragma unroll
        for (int p = 0; p < 4; p++) {
            int n  = w*64 + p*16 + ((lane >> 4) & 1)*8 + (lane & 7);
            int kh = (lane >> 3) & 1;
            unsigned addr = bsb + (unsigned)(n*WROW + kk*16 + kh*8)*2u;
            ldsm_x4(b2[2*p][0], b2[2*p][1], b2[2*p+1][0], b2[2*p+1][1], addr);
        }
        #pragma unroll
        for (int mt = 0; mt < 2; mt++)
            #pragma unroll
            for (int nt = 0; nt < 8; nt++)
                mma16816(acc[mt][nt], a[mt][0], a[mt][1], a[mt][2], a[mt][3],
                         b2[nt][0], b2[nt][1]);
    }

    float sum[2][2] = {{0.f,0.f},{0.f,0.f}};
    float sq [2][2] = {{0.f,0.f},{0.f,0.f}};
    #pragma unroll
    for (int mt = 0; mt < 2; mt++) {
        int row = mt*16 + (lane >> 2);
        #pragma unroll
        for (int nt = 0; nt < 8; nt++) {
            int col = w*64 + nt*8 + (lane & 3)*2;
            float2 h0 = *(const float2*)(g_h + (size_t)(t0+row)*EMBED + col);
            float2 h1 = *(const float2*)(g_h + (size_t)(t0+row+8)*EMBED + col);
            acc[mt][nt][0] += h0.x; acc[mt][nt][1] += h0.y;
            acc[mt][nt][2] += h1.x; acc[mt][nt][3] += h1.y;
            sum[mt][0] += acc[mt][nt][0] + acc[mt][nt][1];
            sum[mt][1] += acc[mt][nt][2] + acc[mt][nt][3];
            sq[mt][0]  += acc[mt][nt][0]*acc[mt][nt][0] + acc[mt][nt][1]*acc[mt][nt][1];
            sq[mt][1]  += acc[mt][nt][2]*acc[mt][nt][2] + acc[mt][nt][3]*acc[mt][nt][3];
        }
    }
    #pragma unroll
    for (int o = 1; o < 4; o <<= 1) {
        #pragma unroll
        for (int mt = 0; mt < 2; mt++)
            #pragma unroll
            for (int hf = 0; hf < 2; hf++) {
                sum[mt][hf] += __shfl_xor_sync(0xffffffffu, sum[mt][hf], o);
                sq[mt][hf]  += __shfl_xor_sync(0xffffffffu, sq[mt][hf], o);
            }
    }
    if ((lane & 3) == 0) {
        int r0 = lane >> 2;
        #pragma unroll
        for (int mt = 0; mt < 2; mt++)
            #pragma unroll
            for (int hf = 0; hf < 2; hf++) {
                int row = mt*16 + hf*8 + r0;
                part_s[row*8 + w] = sum[mt][hf];
                part_q[row*8 + w] = sq[mt][hf];
            }
    }
    __syncthreads();
    {
        int row = tid >> 3;
        float s1 = part_s[tid], s2 = part_q[tid];
        #pragma unroll
        for (int o = 1; o < 8; o <<= 1) {
            s1 += __shfl_xor_sync(0xffffffffu, s1, o);
            s2 += __shfl_xor_sync(0xffffffffu, s2, o);
        }
        if ((tid & 7) == 0) {
            float mu  = s1 * (1.f/EMBED);
            float var = s2 * (1.f/EMBED) - mu*mu;
            stats[row] = make_float2(mu, rsqrtf(var + 1e-5f));
        }
    }
    __syncthreads();
    #pragma unroll
    for (int mt = 0; mt < 2; mt++) {
        int row = mt*16 + (lane >> 2);
        float2 s0 = stats[row], s1 = stats[row+8];
        #pragma unroll
        for (int nt = 0; nt < 8; nt++) {
            int col = w*64 + nt*8 + (lane & 3)*2;
            float2 gv = *(const float2*)(gg + col);
            float2 bv = *(const float2*)(bb + col);
            float2 o0, o1;
            o0.x = (acc[mt][nt][0] - s0.x)*s0.y*gv.x + bv.x;
            o0.y = (acc[mt][nt][1] - s0.x)*s0.y*gv.y + bv.y;
            o1.x = (acc[mt][nt][2] - s1.x)*s1.y*gv.x + bv.x;
            o1.y = (acc[mt][nt][3] - s1.x)*s1.y*gv.y + bv.y;
            *(float2*)(g_h + (size_t)(t0+row)*EMBED + col)   = o0;
            *(float2*)(g_h + (size_t)(t0+row+8)*EMBED + col) = o1;
        }
    }
}

// ---------------- rank-8 FFN hidden, 16 tokens/CTA -> bf16 -------------------------
__global__ __launch_bounds__(256) void ffn1_kernel(const float* __restrict__ phi,
                                                   const float* __restrict__ W1) {
    __shared__ float cs[16*8];
    const int tid = threadIdx.x;
    const int t0 = blockIdx.x*16;
    if (tid < 128) {
        int tok = tid >> 3, w = tid & 7;
        cs[tid] = cosf(g_h[(size_t)(t0+tok)*EMBED + w] + phi[w]);
    }
    __syncthreads();
    #pragma unroll
    for (int it = 0; it < 8; it++) {
        int j = tid + it*256;
        const float4* w4 = (const float4*)(W1 + (size_t)j*NW);
        float4 w0 = w4[0], w1 = w4[1];
        #pragma unroll
        for (int tok = 0; tok < 16; tok++) {
            const float* c = cs + tok*8;
            float a = c[0]*w0.x + c[1]*w0.y + c[2]*w0.z + c[3]*w0.w
                    + c[4]*w1.x + c[5]*w1.y + c[6]*w1.z + c[7]*w1.w;
            g_fb[(size_t)(t0+tok)*FFN_ + j] = __float2bfloat16(fmaxf(a, 0.f));
        }
    }
}

// ---------------- residual + layernorm (post-W2; tmp in bf16) ----------------------
__global__ __launch_bounds__(128) void addln_kernel(const float* __restrict__ gg,
                                                    const float* __restrict__ bb) {
    int t = blockIdx.x;
    int tid = threadIdx.x;
    __shared__ float r1[4], r2[4];
    float v[4]; float s = 0.f;
    #pragma unroll
    for (int q=0;q<4;q++) {
        int e = tid + q*128;
        float val = g_h[(size_t)t*EMBED+e] + __bfloat162float(g_tmpb[(size_t)t*EMBED+e]);
        v[q]=val; s+=val;
    }
    #pragma unroll
    for (int o=16;o;o>>=1) s += __shfl_down_sync(0xffffffffu, s, o);
    if ((tid&31)==0) r1[tid>>5]=s;
    __syncthreads();
    float mu = (r1[0]+r1[1]+r1[2]+r1[3]) * (1.f/EMBED);
    float vs = 0.f;
    #pragma unroll
    for (int q=0;q<4;q++) { float d=v[q]-mu; vs += d*d; }
    #pragma unroll
    for (int o=16;o;o>>=1) vs += __shfl_down_sync(0xffffffffu, vs, o);
    if ((tid&31)==0) r2[tid>>5]=vs;
    __syncthreads();
    float var = (r2[0]+r2[1]+r2[2]+r2[3]) * (1.f/EMBED);
    float inv = rsqrtf(var + 1e-5f);
    #pragma unroll
    for (int q=0;q<4;q++) {
        int e = tid + q*128;
        g_h[(size_t)t*EMBED+e] = (v[q]-mu)*inv*gg[e] + bb[e];
    }
}

// ---------------- mean pool, 2-phase -----------------------------------------------
__global__ void pool1_kernel() {
    int ch = blockIdx.x, b = blockIdx.y, e = threadIdx.x;
    float s = 0.f;
    #pragma unroll 4
    for (int i = 0; i < 128; i++)
        s += g_h[((size_t)b*SEQ + ch*128 + i)*EMBED + e];
    g_poolp[((size_t)b*16 + ch)*EMBED + e] = s;
}
__global__ void pool2_kernel() {
    int b = blockIdx.x, e = threadIdx.x;
    float s = 0.f;
    #pragma unroll
    for (int ch = 0; ch < 16; ch++)
        s += g_poolp[((size_t)b*16 + ch)*EMBED + e];
    g_pool[b*EMBED + e] = s * (1.f/SEQ);
}

// ---------------- classifier -------------------------------------------------------
__global__ void cls_kernel(const float* __restrict__ Wc, const float* __restrict__ bc,
                           float* __restrict__ out) {
    int idx = blockIdx.x*blockDim.x + threadIdx.x;
    if (idx >= BATCH*CLASSES) return;
    int b = idx / CLASSES, c = idx % CLASSES;
    const float* p = g_pool + b*EMBED;
    const float* w = Wc + (size_t)c*EMBED;
    float s = bc[c];
    for (int e=0;e<EMBED;e++) s = fmaf(p[e], w[e], s);
    out[idx] = s;
}

// ---------------- launch -----------------------------------------------------------
extern "C" void kernel_launch(void* const* d_in, const int* in_sizes, int n_in,
                              void* d_out, int out_size) {
    const float* x     = (const float*)d_in[0];
    const float* Wi    = (const float*)d_in[1];
    const float* bi    = (const float*)d_in[2];
    const float* theta = (const float*)d_in[3];
    const float* Wproj = (const float*)d_in[4];
    const float* Wq    = (const float*)d_in[5];
    const float* Wk    = (const float*)d_in[6];
    const float* Wv    = (const float*)d_in[7];
    const float* Wo    = (const float*)d_in[8];
    const float* g1    = (const float*)d_in[9];
    const float* b1    = (const float*)d_in[10];
    const float* phi   = (const float*)d_in[11];
    const float* W1    = (const float*)d_in[12];
    const float* W2    = (const float*)d_in[13];
    const float* g2    = (const float*)d_in[14];
    const float* b2    = (const float*)d_in[15];
    const float* Wc    = (const float*)d_in[16];
    const float* bc    = (const float*)d_in[17];
    float* out = (float*)d_out;

    float *p_h, *p_m;
    __nv_bfloat16 *p_tmpb, *p_fb, *p_w2b, *p_ub, *p_xcat, *p_wcat;
    cudaGetSymbolAddress((void**)&p_h,    g_h);
    cudaGetSymbolAddress((void**)&p_tmpb, g_tmpb);
    cudaGetSymbolAddress((void**)&p_fb,   g_fb);
    cudaGetSymbolAddress((void**)&p_w2b,  g_w2b);
    cudaGetSymbolAddress((void**)&p_ub,   g_ub);
    cudaGetSymbolAddress((void**)&p_m,    g_m);
    cudaGetSymbolAddress((void**)&p_xcat, g_xcat);
    cudaGetSymbolAddress((void**)&p_wcat, g_wcat);

    cudaFuncSetAttribute(gemm_bf16, cudaFuncAttributeMaxDynamicSharedMemorySize, GSMEM);
    cudaFuncSetAttribute(gemm_wo_ln, cudaFuncAttributeMaxDynamicSharedMemorySize, WO_SMEM);

    setup1_kernel<<<SB_EFF, 256>>>(x, Wi, W2, Wq, Wk, Wv, Wproj);
    setup2_kernel<<<130, 512>>>(Wo);

    dim3 gg(EMBED/128, TOK/128);   // (4, 128)
    gemm_bf16<<<gg, 256, GSMEM>>>(p_xcat, p_wcat, p_h, nullptr, 768, EMBED, bi, 1);

    for (int l = 0; l < 2; l++) {
        stats_kernel<<<dim3(9, BATCH, 4), 256>>>(theta + l*NW);
        gemm_wo_ln<<<TOK/32, 256, WO_SMEM>>>(theta + l*NW, p_m + (size_t)l*HEADS*64,
                                             p_ub + (size_t)l*EMBED*64,
                                             g1 + l*EMBED, b1 + l*EMBED);
        ffn1_kernel<<<TOK/16, 256>>>(phi + l*NW, W1 + (size_t)l*FFN_*NW);
        gemm_bf16<<<gg, 256, GSMEM>>>(p_fb, p_w2b + (size_t)l*EMBED*FFN_,
                                      nullptr, p_tmpb, FFN_, EMBED, nullptr, 0);
        addln_kernel<<<TOK, 128>>>(g2 + l*EMBED, b2 + l*EMBED);
    }

    pool1_kernel<<<dim3(16, BATCH), EMBED>>>();
    pool2_kernel<<<BATCH, EMBED>>>();
    cls_kernel<<<(BATCH*CLASSES + 255)/256, 256>>>(Wc, bc, out);
}